// round 1
// baseline (speedup 1.0000x reference)
#include <cuda_runtime.h>

#define SEQ    2048
#define DMODEL 1024
#define NH     16
#define HD     64
#define BATCH  2

// Scratch: [3 matrices][B*NH heads][SEQ][HD], head-major for coalesced attention.
__device__ float g_qkv[3ULL * BATCH * NH * SEQ * HD];

// ---------------------------------------------------------------------------
// Kernel A: Y = X @ W for W in {Wq,Wk,Wv}, RoPE fused in epilogue,
// scatter to g_qkv[mat][b*NH+h][s][d].
// Grid: (DMODEL/64, B*SEQ/64, 3), Block: 256
// ---------------------------------------------------------------------------
__global__ __launch_bounds__(256) void qkv_gemm_rope_kernel(
    const float* __restrict__ X,
    const float* __restrict__ Wq,
    const float* __restrict__ Wk,
    const float* __restrict__ Wv,
    const float* __restrict__ sinT,   // [SEQ][HD/2]
    const float* __restrict__ cosT)   // [SEQ][HD/2]
{
    const int mat = blockIdx.z;
    const float* W = (mat == 0) ? Wq : (mat == 1) ? Wk : Wv;

    __shared__ float As[64][17];   // [row][k]  (+1 pad)
    __shared__ float Bs[16][65];   // [k][col]  (+1 pad)

    const int tid = threadIdx.x;
    const int tx  = tid & 15;       // micro-tile col group
    const int ty  = tid >> 4;       // micro-tile row group
    const int row0 = blockIdx.y * 64;
    const int col0 = blockIdx.x * 64;

    const int la_r = tid >> 2;           // 0..63
    const int la_c = (tid & 3) * 4;      // 0,4,8,12
    const int lb_r = tid >> 4;           // 0..15
    const int lb_c = (tid & 15) * 4;     // 0..60

    float acc[4][4] = {};

    for (int k0 = 0; k0 < DMODEL; k0 += 16) {
        float4 av = *(const float4*)(X + (size_t)(row0 + la_r) * DMODEL + k0 + la_c);
        As[la_r][la_c + 0] = av.x;
        As[la_r][la_c + 1] = av.y;
        As[la_r][la_c + 2] = av.z;
        As[la_r][la_c + 3] = av.w;

        float4 bv = *(const float4*)(W + (size_t)(k0 + lb_r) * DMODEL + col0 + lb_c);
        Bs[lb_r][lb_c + 0] = bv.x;
        Bs[lb_r][lb_c + 1] = bv.y;
        Bs[lb_r][lb_c + 2] = bv.z;
        Bs[lb_r][lb_c + 3] = bv.w;

        __syncthreads();

        #pragma unroll
        for (int kk = 0; kk < 16; kk++) {
            float a[4], b[4];
            #pragma unroll
            for (int i = 0; i < 4; i++) a[i] = As[ty * 4 + i][kk];
            #pragma unroll
            for (int j = 0; j < 4; j++) b[j] = Bs[kk][tx * 4 + j];
            #pragma unroll
            for (int i = 0; i < 4; i++)
                #pragma unroll
                for (int j = 0; j < 4; j++)
                    acc[i][j] += a[i] * b[j];
        }
        __syncthreads();
    }

    // Epilogue: RoPE on interleaved pairs, scatter head-major.
    #pragma unroll
    for (int i = 0; i < 4; i++) {
        const int row = row0 + ty * 4 + i;     // global row in (B*SEQ)
        const int s   = row & (SEQ - 1);
        const int b   = row >> 11;             // row / SEQ
        #pragma unroll
        for (int j0 = 0; j0 < 4; j0 += 2) {
            const int col = col0 + tx * 4 + j0;
            const int h   = col >> 6;          // col / HD
            const int d   = col & (HD - 1);
            const int pi  = d >> 1;
            const float sn = sinT[s * (HD / 2) + pi];
            const float cs = cosT[s * (HD / 2) + pi];
            const float x1 = acc[i][j0];
            const float x2 = acc[i][j0 + 1];
            const size_t base =
                ((size_t)(mat * (BATCH * NH) + b * NH + h) * SEQ + s) * HD + d;
            g_qkv[base]     = x1 * cs - x2 * sn;
            g_qkv[base + 1] = x2 * cs + x1 * sn;
        }
    }
}

// ---------------------------------------------------------------------------
// Kernel B: flash attention, one (b,h) head and 64 q-rows per block.
// Grid: (SEQ/64, B*NH), Block: 256. Static smem = 48KB exactly.
// ---------------------------------------------------------------------------
__global__ __launch_bounds__(256) void attn_kernel(float* __restrict__ out)
{
    __shared__ float Qs [64][64];   // [q][d]
    __shared__ float KVs[64][64];   // K phase: [d][(c+d)&63] swizzled; V phase: [c][d]
    __shared__ float Ps [64][64];   // [q][c]

    const int bh = blockIdx.y;                  // 0..31
    const int q0 = blockIdx.x * 64;
    const float* Qg = g_qkv + (size_t)bh * SEQ * HD;
    const float* Kg = g_qkv + (size_t)(BATCH * NH + bh) * SEQ * HD;
    const float* Vg = g_qkv + (size_t)(2 * BATCH * NH + bh) * SEQ * HD;

    const int tid = threadIdx.x;
    const int tx  = tid & 15;
    const int ty  = tid >> 4;

    // Load Q tile (pre-scaled by 1/sqrt(HD))
    #pragma unroll
    for (int e = tid; e < 4096; e += 256) {
        int r = e >> 6, d = e & 63;
        Qs[r][d] = Qg[(size_t)(q0 + r) * HD + d] * 0.125f;
    }

    float m[4], l[4], O[4][4];
    #pragma unroll
    for (int i = 0; i < 4; i++) {
        m[i] = -1e30f; l[i] = 0.f;
        #pragma unroll
        for (int j = 0; j < 4; j++) O[i][j] = 0.f;
    }

    for (int kv0 = 0; kv0 < SEQ; kv0 += 64) {
        __syncthreads();   // previous V reads done before K overwrite
        // K tile, d-major with (c+d)&63 column swizzle (conflict-free both ways)
        #pragma unroll
        for (int e = tid; e < 4096; e += 256) {
            int c = e >> 6, d = e & 63;
            KVs[d][(c + d) & 63] = Kg[(size_t)(kv0 + c) * HD + d];
        }
        __syncthreads();

        // S = Q K^T  (64x64x64)
        float sv[4][4] = {};
        #pragma unroll 8
        for (int kk = 0; kk < 64; kk++) {
            float a[4], b[4];
            #pragma unroll
            for (int i = 0; i < 4; i++) a[i] = Qs[ty * 4 + i][kk];
            #pragma unroll
            for (int j = 0; j < 4; j++) b[j] = KVs[kk][(tx * 4 + j + kk) & 63];
            #pragma unroll
            for (int i = 0; i < 4; i++)
                #pragma unroll
                for (int j = 0; j < 4; j++)
                    sv[i][j] += a[i] * b[j];
        }

        // Online softmax (16-lane tx-group reductions; xor<16 stays in half-warp)
        #pragma unroll
        for (int i = 0; i < 4; i++) {
            float mt = fmaxf(fmaxf(sv[i][0], sv[i][1]), fmaxf(sv[i][2], sv[i][3]));
            #pragma unroll
            for (int k = 8; k >= 1; k >>= 1)
                mt = fmaxf(mt, __shfl_xor_sync(0xffffffffu, mt, k));
            const float newm = fmaxf(m[i], mt);
            const float sc   = __expf(m[i] - newm);
            float rs = 0.f;
            #pragma unroll
            for (int j = 0; j < 4; j++) {
                sv[i][j] = __expf(sv[i][j] - newm);
                rs += sv[i][j];
            }
            #pragma unroll
            for (int k = 8; k >= 1; k >>= 1)
                rs += __shfl_xor_sync(0xffffffffu, rs, k);
            l[i] = l[i] * sc + rs;
            m[i] = newm;
            #pragma unroll
            for (int j = 0; j < 4; j++) O[i][j] *= sc;
            *(float4*)&Ps[ty * 4 + i][tx * 4] =
                make_float4(sv[i][0], sv[i][1], sv[i][2], sv[i][3]);
        }
        __syncthreads();   // P complete; K reads complete

        // V tile (direct layout, reusing KVs)
        #pragma unroll
        for (int e = tid; e < 4096; e += 256) {
            int c = e >> 6, d = e & 63;
            KVs[c][d] = Vg[(size_t)(kv0 + c) * HD + d];
        }
        __syncthreads();

        // O += P V  (64x64x64)
        #pragma unroll 8
        for (int kk = 0; kk < 64; kk++) {
            float a[4], b[4];
            #pragma unroll
            for (int i = 0; i < 4; i++) a[i] = Ps[ty * 4 + i][kk];
            #pragma unroll
            for (int j = 0; j < 4; j++) b[j] = KVs[kk][tx * 4 + j];
            #pragma unroll
            for (int i = 0; i < 4; i++)
                #pragma unroll
                for (int j = 0; j < 4; j++)
                    O[i][j] += a[i] * b[j];
        }
    }

    // Normalize + write out[b][s][h*HD+d]
    const int b = bh >> 4;
    const int h = bh & 15;
    #pragma unroll
    for (int i = 0; i < 4; i++) {
        const float inv = 1.0f / l[i];
        const int srow = q0 + ty * 4 + i;
        float4 v = make_float4(O[i][0] * inv, O[i][1] * inv,
                               O[i][2] * inv, O[i][3] * inv);
        *(float4*)(out + ((size_t)b * SEQ + srow) * DMODEL + h * HD + tx * 4) = v;
    }
}

extern "C" void kernel_launch(void* const* d_in, const int* in_sizes, int n_in,
                              void* d_out, int out_size)
{
    const float* X    = (const float*)d_in[0];
    const float* Wq   = (const float*)d_in[1];
    const float* Wk   = (const float*)d_in[2];
    const float* Wv   = (const float*)d_in[3];
    const float* sinT = (const float*)d_in[4];
    const float* cosT = (const float*)d_in[5];
    float* out = (float*)d_out;

    dim3 g1(DMODEL / 64, (BATCH * SEQ) / 64, 3);
    qkv_gemm_rope_kernel<<<g1, 256>>>(X, Wq, Wk, Wv, sinT, cosT);

    dim3 g2(SEQ / 64, BATCH * NH);
    attn_kernel<<<g2, 256>>>(out);
}

// round 4
// speedup vs baseline: 1.6402x; 1.6402x over previous
#include <cuda_runtime.h>

#define SEQ    2048
#define DM     1024
#define NH     16
#define HD     64
#define BATCH  2

// Scratch: [3 matrices][B*NH heads][SEQ][HD]
__device__ float g_qkv[3ULL * BATCH * NH * SEQ * HD];

// ---------------------------------------------------------------------------
// TF32 helpers: 3xTF32 split product keeps ~fp32 accuracy on tensor cores.
// ---------------------------------------------------------------------------
__device__ __forceinline__ unsigned f2tf(float x) {
    unsigned u;
    asm("cvt.rna.tf32.f32 %0, %1;" : "=r"(u) : "f"(x));
    return u;
}
__device__ __forceinline__ void split_tf(float x, unsigned& hi, unsigned& lo) {
    hi = f2tf(x);
    lo = f2tf(x - __uint_as_float(hi));
}
__device__ __forceinline__ void mma_tf32(float d[4], const unsigned a[4], const unsigned b[2]) {
    asm volatile(
        "mma.sync.aligned.m16n8k8.row.col.f32.tf32.tf32.f32 "
        "{%0,%1,%2,%3},{%4,%5,%6,%7},{%8,%9},{%0,%1,%2,%3};\n"
        : "+f"(d[0]), "+f"(d[1]), "+f"(d[2]), "+f"(d[3])
        : "r"(a[0]), "r"(a[1]), "r"(a[2]), "r"(a[3]), "r"(b[0]), "r"(b[1]));
}

// ---------------------------------------------------------------------------
// Kernel A: Y = X @ W (3 mats), RoPE fused, scatter head-major to g_qkv.
// Block 256 thr (8 warps, 4x2), tile 128x64, BK=16. Grid (16, 32, 3).
// ---------------------------------------------------------------------------
__global__ __launch_bounds__(256) void qkv_gemm_rope(
    const float* __restrict__ X,
    const float* __restrict__ Wq,
    const float* __restrict__ Wk,
    const float* __restrict__ Wv,
    const float* __restrict__ sinT,
    const float* __restrict__ cosT)
{
    const int mat = blockIdx.z;
    const float* W = (mat == 0) ? Wq : (mat == 1) ? Wk : Wv;

    __shared__ float As[128][20];   // stride 20: conflict-free A-frag loads
    __shared__ float Bs[16][72];    // stride 72: conflict-free B-frag loads

    const int tid  = threadIdx.x;
    const int wid  = tid >> 5;
    const int lane = tid & 31;
    const int wm   = wid >> 1;          // 0..3
    const int wn   = wid & 1;           // 0..1
    const int qr   = lane >> 2;         // t/4
    const int qc   = lane & 3;          // t%4
    const int row0 = blockIdx.y * 128;
    const int col0 = blockIdx.x * 64;

    float acc[2][4][4];
    #pragma unroll
    for (int mi = 0; mi < 2; mi++)
        #pragma unroll
        for (int j = 0; j < 4; j++)
            #pragma unroll
            for (int c = 0; c < 4; c++) acc[mi][j][c] = 0.f;

    for (int k0 = 0; k0 < DM; k0 += 16) {
        #pragma unroll
        for (int i = 0; i < 2; i++) {
            int e = tid + 256 * i;
            int r = e >> 2, c4 = (e & 3) << 2;
            *(float4*)&As[r][c4] =
                *(const float4*)(X + (size_t)(row0 + r) * DM + k0 + c4);
        }
        {
            int r = tid >> 4, c4 = (tid & 15) << 2;
            *(float4*)&Bs[r][c4] =
                *(const float4*)(W + (size_t)(k0 + r) * DM + col0 + c4);
        }
        __syncthreads();

        #pragma unroll
        for (int ks = 0; ks < 2; ks++) {
            const int kb = ks * 8;
            unsigned ahi[2][4], alo[2][4];
            #pragma unroll
            for (int mi = 0; mi < 2; mi++) {
                int rb = wm * 32 + mi * 16;
                split_tf(As[rb + qr    ][kb + qc    ], ahi[mi][0], alo[mi][0]);
                split_tf(As[rb + qr + 8][kb + qc    ], ahi[mi][1], alo[mi][1]);
                split_tf(As[rb + qr    ][kb + qc + 4], ahi[mi][2], alo[mi][2]);
                split_tf(As[rb + qr + 8][kb + qc + 4], ahi[mi][3], alo[mi][3]);
            }
            #pragma unroll
            for (int j = 0; j < 4; j++) {
                int nb = wn * 32 + j * 8;
                unsigned bhi[2], blo[2];
                split_tf(Bs[kb + qc    ][nb + qr], bhi[0], blo[0]);
                split_tf(Bs[kb + qc + 4][nb + qr], bhi[1], blo[1]);
                #pragma unroll
                for (int mi = 0; mi < 2; mi++) {
                    mma_tf32(acc[mi][j], ahi[mi], bhi);
                    mma_tf32(acc[mi][j], ahi[mi], blo);
                    mma_tf32(acc[mi][j], alo[mi], bhi);
                }
            }
        }
        __syncthreads();
    }

    // Epilogue: RoPE pairs (c0,c1) / (c2,c3) are exactly (even,odd) columns.
    const int h = blockIdx.x;   // col0 / 64
    #pragma unroll
    for (int mi = 0; mi < 2; mi++) {
        #pragma unroll
        for (int half = 0; half < 2; half++) {
            int rg = row0 + wm * 32 + mi * 16 + qr + half * 8;
            int s  = rg & (SEQ - 1);
            int b  = rg >> 11;
            #pragma unroll
            for (int j = 0; j < 4; j++) {
                float x1 = acc[mi][j][half * 2 + 0];
                float x2 = acc[mi][j][half * 2 + 1];
                int hd = wn * 32 + j * 8 + 2 * qc;
                int pi = hd >> 1;
                float sn = sinT[s * (HD / 2) + pi];
                float cs = cosT[s * (HD / 2) + pi];
                size_t base =
                    ((size_t)((mat * BATCH + b) * NH + h) * SEQ + s) * HD + hd;
                *(float2*)&g_qkv[base] =
                    make_float2(x1 * cs - x2 * sn, x2 * cs + x1 * sn);
            }
        }
    }
}

// ---------------------------------------------------------------------------
// Kernel B: flash attention with TF32x3 MMAs. Block 128 thr (4 warps),
// each warp owns 16 q-rows x full 64 cols (softmax fully warp-local).
// Grid (SEQ/64, B*NH).
// ---------------------------------------------------------------------------
__global__ __launch_bounds__(128) void attn_kernel(float* __restrict__ out)
{
    __shared__ float KV[64][72];   // K phase then V phase (stride 72: conflict-free)
    __shared__ float Ps[64][72];   // Q staging, then P tiles

    const int tid  = threadIdx.x;
    const int wid  = tid >> 5;
    const int lane = tid & 31;
    const int qr   = lane >> 2;
    const int qc   = lane & 3;
    const int bh   = blockIdx.y;
    const int q0   = blockIdx.x * 64;
    const int wr   = wid * 16;

    const float* Qg = g_qkv + (size_t)bh * SEQ * HD;
    const float* Kg = g_qkv + (size_t)(BATCH * NH + bh) * SEQ * HD;
    const float* Vg = g_qkv + (size_t)(2 * BATCH * NH + bh) * SEQ * HD;

    // Stage Q (pre-scaled), then keep it in registers as pre-split TF32 frags.
    #pragma unroll
    for (int i = 0; i < 8; i++) {
        int e = tid + 128 * i;
        int r = e >> 4, c4 = (e & 15) << 2;
        float4 v = *(const float4*)(Qg + (size_t)(q0 + r) * HD + c4);
        v.x *= 0.125f; v.y *= 0.125f; v.z *= 0.125f; v.w *= 0.125f;
        *(float4*)&Ps[r][c4] = v;
    }
    __syncthreads();

    unsigned qhi[8][4], qlo[8][4];
    #pragma unroll
    for (int kk = 0; kk < 8; kk++) {
        int kb = kk * 8;
        split_tf(Ps[wr + qr    ][kb + qc    ], qhi[kk][0], qlo[kk][0]);
        split_tf(Ps[wr + qr + 8][kb + qc    ], qhi[kk][1], qlo[kk][1]);
        split_tf(Ps[wr + qr    ][kb + qc + 4], qhi[kk][2], qlo[kk][2]);
        split_tf(Ps[wr + qr + 8][kb + qc + 4], qhi[kk][3], qlo[kk][3]);
    }

    float m0 = -1e30f, m1 = -1e30f, l0 = 0.f, l1 = 0.f;
    float O[8][4];
    #pragma unroll
    for (int j = 0; j < 8; j++)
        #pragma unroll
        for (int c = 0; c < 4; c++) O[j][c] = 0.f;

    for (int kv0 = 0; kv0 < SEQ; kv0 += 64) {
        __syncthreads();   // previous PV reads of KV/Ps complete
        #pragma unroll
        for (int i = 0; i < 8; i++) {
            int e = tid + 128 * i;
            int r = e >> 4, c4 = (e & 15) << 2;
            *(float4*)&KV[r][c4] =
                *(const float4*)(Kg + (size_t)(kv0 + r) * HD + c4);
        }
        __syncthreads();

        // S = Q K^T : 8 n-tiles, 8 k-steps
        float S[8][4];
        #pragma unroll
        for (int j = 0; j < 8; j++)
            #pragma unroll
            for (int c = 0; c < 4; c++) S[j][c] = 0.f;

        #pragma unroll
        for (int kk = 0; kk < 8; kk++) {
            int kb = kk * 8;
            #pragma unroll
            for (int j = 0; j < 8; j++) {
                int nb = j * 8;
                unsigned bhi[2], blo[2];
                split_tf(KV[nb + qr][kb + qc    ], bhi[0], blo[0]);
                split_tf(KV[nb + qr][kb + qc + 4], bhi[1], blo[1]);
                mma_tf32(S[j], qhi[kk], bhi);
                mma_tf32(S[j], qhi[kk], blo);
                mma_tf32(S[j], qlo[kk], bhi);
            }
        }
        __syncthreads();   // K reads done

        // Load V into KV (overlaps with register softmax below)
        #pragma unroll
        for (int i = 0; i < 8; i++) {
            int e = tid + 128 * i;
            int r = e >> 4, c4 = (e & 15) << 2;
            *(float4*)&KV[r][c4] =
                *(const float4*)(Vg + (size_t)(kv0 + r) * HD + c4);
        }

        // Online softmax (rows qr and qr+8; quad shuffle covers 64 cols)
        float mx0 = -1e30f, mx1 = -1e30f;
        #pragma unroll
        for (int j = 0; j < 8; j++) {
            mx0 = fmaxf(mx0, fmaxf(S[j][0], S[j][1]));
            mx1 = fmaxf(mx1, fmaxf(S[j][2], S[j][3]));
        }
        #pragma unroll
        for (int k = 1; k <= 2; k <<= 1) {
            mx0 = fmaxf(mx0, __shfl_xor_sync(0xffffffffu, mx0, k));
            mx1 = fmaxf(mx1, __shfl_xor_sync(0xffffffffu, mx1, k));
        }
        float nm0 = fmaxf(m0, mx0), nm1 = fmaxf(m1, mx1);
        float sc0 = __expf(m0 - nm0), sc1 = __expf(m1 - nm1);
        m0 = nm0; m1 = nm1;
        float s0 = 0.f, s1 = 0.f;
        #pragma unroll
        for (int j = 0; j < 8; j++) {
            S[j][0] = __expf(S[j][0] - nm0);
            S[j][1] = __expf(S[j][1] - nm0);
            S[j][2] = __expf(S[j][2] - nm1);
            S[j][3] = __expf(S[j][3] - nm1);
            s0 += S[j][0] + S[j][1];
            s1 += S[j][2] + S[j][3];
            *(float2*)&Ps[wr + qr    ][j * 8 + 2 * qc] = make_float2(S[j][0], S[j][1]);
            *(float2*)&Ps[wr + qr + 8][j * 8 + 2 * qc] = make_float2(S[j][2], S[j][3]);
            O[j][0] *= sc0; O[j][1] *= sc0; O[j][2] *= sc1; O[j][3] *= sc1;
        }
        #pragma unroll
        for (int k = 1; k <= 2; k <<= 1) {
            s0 += __shfl_xor_sync(0xffffffffu, s0, k);
            s1 += __shfl_xor_sync(0xffffffffu, s1, k);
        }
        l0 = l0 * sc0 + s0;
        l1 = l1 * sc1 + s1;
        __syncthreads();   // V and P visible

        // O += P V : 8 d-tiles, 8 kv-steps
        #pragma unroll
        for (int kk = 0; kk < 8; kk++) {
            int kb = kk * 8;
            unsigned phi[4], plo[4];
            split_tf(Ps[wr + qr    ][kb + qc    ], phi[0], plo[0]);
            split_tf(Ps[wr + qr + 8][kb + qc    ], phi[1], plo[1]);
            split_tf(Ps[wr + qr    ][kb + qc + 4], phi[2], plo[2]);
            split_tf(Ps[wr + qr + 8][kb + qc + 4], phi[3], plo[3]);
            #pragma unroll
            for (int j = 0; j < 8; j++) {
                int nb = j * 8;
                unsigned bhi[2], blo[2];
                split_tf(KV[kb + qc    ][nb + qr], bhi[0], blo[0]);
                split_tf(KV[kb + qc + 4][nb + qr], bhi[1], blo[1]);
                mma_tf32(O[j], phi, bhi);
                mma_tf32(O[j], phi, blo);
                mma_tf32(O[j], plo, bhi);
            }
        }
    }

    // Epilogue: normalize and write out[b][s][h*64 + d]
    const int b = bh >> 4, h = bh & 15;
    const float inv0 = 1.f / l0, inv1 = 1.f / l1;
    const int rg0 = q0 + wr + qr;
    #pragma unroll
    for (int j = 0; j < 8; j++) {
        int col = h * HD + j * 8 + 2 * qc;
        *(float2*)(out + (size_t)(b * SEQ + rg0    ) * DM + col) =
            make_float2(O[j][0] * inv0, O[j][1] * inv0);
        *(float2*)(out + (size_t)(b * SEQ + rg0 + 8) * DM + col) =
            make_float2(O[j][2] * inv1, O[j][3] * inv1);
    }
}

extern "C" void kernel_launch(void* const* d_in, const int* in_sizes, int n_in,
                              void* d_out, int out_size)
{
    const float* X    = (const float*)d_in[0];
    const float* Wq   = (const float*)d_in[1];
    const float* Wk   = (const float*)d_in[2];
    const float* Wv   = (const float*)d_in[3];
    const float* sinT = (const float*)d_in[4];
    const float* cosT = (const float*)d_in[5];
    float* out = (float*)d_out;

    dim3 g1(DM / 64, (BATCH * SEQ) / 128, 3);
    qkv_gemm_rope<<<g1, 256>>>(X, Wq, Wk, Wv, sinT, cosT);

    dim3 g2(SEQ / 64, BATCH * NH);
    attn_kernel<<<g2, 128>>>(out);
}

// round 5
// speedup vs baseline: 3.3912x; 2.0675x over previous
#include <cuda_runtime.h>
#include <cuda_bf16.h>

#define SEQ    2048
#define DM     1024
#define NH     16
#define HD     64
#define BATCH  2

// Scratch: Q [bh][s][d], K [bh][s][d], V [bh][d][s]  (V transposed for attn)
__device__ float g_qkv[3ULL * BATCH * NH * SEQ * HD];

// ---------------------------------------------------------------------------
// bf16 split helpers: x = hi + lo with bf16 hi/lo; 3-term product ~fp32-ish.
// ---------------------------------------------------------------------------
__device__ __forceinline__ void split2(float x, float y, unsigned& hi, unsigned& lo) {
    __nv_bfloat162 h = __float22bfloat162_rn(make_float2(x, y));
    float hx = __bfloat162float(__low2bfloat16(h));
    float hy = __bfloat162float(__high2bfloat16(h));
    __nv_bfloat162 l = __float22bfloat162_rn(make_float2(x - hx, y - hy));
    hi = *reinterpret_cast<unsigned*>(&h);
    lo = *reinterpret_cast<unsigned*>(&l);
}
__device__ __forceinline__ void mma_bf16(float d[4], const unsigned a[4], const unsigned b[2]) {
    asm volatile(
        "mma.sync.aligned.m16n8k16.row.col.f32.bf16.bf16.f32 "
        "{%0,%1,%2,%3},{%4,%5,%6,%7},{%8,%9},{%0,%1,%2,%3};\n"
        : "+f"(d[0]), "+f"(d[1]), "+f"(d[2]), "+f"(d[3])
        : "r"(a[0]), "r"(a[1]), "r"(a[2]), "r"(a[3]), "r"(b[0]), "r"(b[1]));
}

// ---------------------------------------------------------------------------
// Kernel A: Y = X @ W (3 mats), RoPE fused. Tile 128x64, BK=32, 256 thr.
// Q/K written [bh][s][d]; V written transposed [bh][d][s].
// Grid (16, 32, 3).
// ---------------------------------------------------------------------------
__global__ __launch_bounds__(256) void qkv_gemm_rope(
    const float* __restrict__ X,
    const float* __restrict__ Wq,
    const float* __restrict__ Wk,
    const float* __restrict__ Wv,
    const float* __restrict__ sinT,
    const float* __restrict__ cosT)
{
    const int mat = blockIdx.z;
    const float* W = (mat == 0) ? Wq : (mat == 1) ? Wk : Wv;

    __shared__ unsigned Ah[128][20], Al[128][20];   // [row][k-pair], stride 20
    __shared__ unsigned Bh[64][20],  Bl[64][20];    // [n][k-pair] (transposed W)

    const int tid  = threadIdx.x;
    const int wid  = tid >> 5;
    const int lane = tid & 31;
    const int wm   = wid >> 1;          // 0..3
    const int wn   = wid & 1;           // 0..1
    const int qr   = lane >> 2;
    const int qc   = lane & 3;
    const int row0 = blockIdx.y * 128;
    const int col0 = blockIdx.x * 64;

    const int ar = tid >> 3;            // A loader: row (+32*i), 8 f4/row
    const int ac = tid & 7;
    const int bc = tid & 15;            // B loader: n-quad
    const int bk2 = tid >> 4;           // k-pair 0..15
    const int bsw = bk2 ^ (2 * (bc & 7));   // store swizzle

    float4 xa[4], wb0, wb1;

    float acc[2][4][4];
    #pragma unroll
    for (int mi = 0; mi < 2; mi++)
        #pragma unroll
        for (int j = 0; j < 4; j++)
            #pragma unroll
            for (int c = 0; c < 4; c++) acc[mi][j][c] = 0.f;

    // prefetch k0 = 0
    #pragma unroll
    for (int i = 0; i < 4; i++)
        xa[i] = *(const float4*)(X + (size_t)(row0 + ar + 32 * i) * DM + 4 * ac);
    wb0 = *(const float4*)(W + (size_t)(2 * bk2) * DM + col0 + 4 * bc);
    wb1 = *(const float4*)(W + (size_t)(2 * bk2 + 1) * DM + col0 + 4 * bc);

    for (int k0 = 0; k0 < DM; k0 += 32) {
        // store staged tile (convert to bf16 planes)
        #pragma unroll
        for (int i = 0; i < 4; i++) {
            int r = ar + 32 * i;
            unsigned h0, l0, h1, l1;
            split2(xa[i].x, xa[i].y, h0, l0);
            split2(xa[i].z, xa[i].w, h1, l1);
            *(uint2*)&Ah[r][2 * ac] = make_uint2(h0, h1);
            *(uint2*)&Al[r][2 * ac] = make_uint2(l0, l1);
        }
        {
            const float* w0 = (const float*)&wb0;
            const float* w1 = (const float*)&wb1;
            #pragma unroll
            for (int j = 0; j < 4; j++) {
                unsigned h, l;
                split2(w0[j], w1[j], h, l);
                Bh[4 * bc + j][bsw] = h;
                Bl[4 * bc + j][bsw] = l;
            }
        }
        __syncthreads();

        if (k0 + 32 < DM) {
            #pragma unroll
            for (int i = 0; i < 4; i++)
                xa[i] = *(const float4*)(X + (size_t)(row0 + ar + 32 * i) * DM + k0 + 32 + 4 * ac);
            wb0 = *(const float4*)(W + (size_t)(k0 + 32 + 2 * bk2) * DM + col0 + 4 * bc);
            wb1 = *(const float4*)(W + (size_t)(k0 + 32 + 2 * bk2 + 1) * DM + col0 + 4 * bc);
        }

        #pragma unroll
        for (int ks = 0; ks < 2; ks++) {
            unsigned ah[2][4], al[2][4];
            #pragma unroll
            for (int mi = 0; mi < 2; mi++) {
                int rb = wm * 32 + mi * 16;
                ah[mi][0] = Ah[rb + qr    ][ks * 8 + qc];
                ah[mi][1] = Ah[rb + qr + 8][ks * 8 + qc];
                ah[mi][2] = Ah[rb + qr    ][ks * 8 + qc + 4];
                ah[mi][3] = Ah[rb + qr + 8][ks * 8 + qc + 4];
                al[mi][0] = Al[rb + qr    ][ks * 8 + qc];
                al[mi][1] = Al[rb + qr + 8][ks * 8 + qc];
                al[mi][2] = Al[rb + qr    ][ks * 8 + qc + 4];
                al[mi][3] = Al[rb + qr + 8][ks * 8 + qc + 4];
            }
            #pragma unroll
            for (int j = 0; j < 4; j++) {
                const int nb = wn * 32 + j * 8;
                const int sw = 2 * (((nb >> 2) + (qr >> 2)) & 7);
                unsigned bh[2], bl[2];
                bh[0] = Bh[nb + qr][(ks * 8 + qc    ) ^ sw];
                bh[1] = Bh[nb + qr][(ks * 8 + qc + 4) ^ sw];
                bl[0] = Bl[nb + qr][(ks * 8 + qc    ) ^ sw];
                bl[1] = Bl[nb + qr][(ks * 8 + qc + 4) ^ sw];
                mma_bf16(acc[0][j], ah[0], bh);
                mma_bf16(acc[0][j], ah[0], bl);
                mma_bf16(acc[0][j], al[0], bh);
                mma_bf16(acc[1][j], ah[1], bh);
                mma_bf16(acc[1][j], ah[1], bl);
                mma_bf16(acc[1][j], al[1], bh);
            }
        }
        __syncthreads();
    }

    // Epilogue: RoPE; Q/K scatter [s][d], V scatter transposed [d][s].
    const int h = blockIdx.x;
    #pragma unroll
    for (int mi = 0; mi < 2; mi++) {
        #pragma unroll
        for (int half = 0; half < 2; half++) {
            int rg = row0 + wm * 32 + mi * 16 + qr + half * 8;
            int s  = rg & (SEQ - 1);
            int b  = rg >> 11;
            const size_t hb = (size_t)((mat * BATCH + b) * NH + h) * SEQ * HD;
            #pragma unroll
            for (int j = 0; j < 4; j++) {
                float x1 = acc[mi][j][half * 2 + 0];
                float x2 = acc[mi][j][half * 2 + 1];
                int hd = wn * 32 + j * 8 + 2 * qc;
                int pi = hd >> 1;
                float sn = sinT[s * (HD / 2) + pi];
                float cs = cosT[s * (HD / 2) + pi];
                float o1 = x1 * cs - x2 * sn;
                float o2 = x2 * cs + x1 * sn;
                if (mat == 2) {
                    g_qkv[hb + (size_t)hd * SEQ + s]       = o1;
                    g_qkv[hb + (size_t)(hd + 1) * SEQ + s] = o2;
                } else {
                    *(float2*)&g_qkv[hb + (size_t)s * HD + hd] = make_float2(o1, o2);
                }
            }
        }
    }
}

// ---------------------------------------------------------------------------
// Kernel B: flash attention, bf16x3 MMAs. 128 thr (4 warps), q-tile 64.
// P stays in registers (C-frag of S == A-frag of PV). Grid (SEQ/64, B*NH).
// ---------------------------------------------------------------------------
__global__ __launch_bounds__(128) void attn_kernel(float* __restrict__ out)
{
    __shared__ unsigned Kh[64][36], Kl[64][36];   // [kv][d-pair]
    __shared__ unsigned Vh[64][36], Vl[64][36];   // [d][kv-pair]; Q staged here first

    const int tid  = threadIdx.x;
    const int wid  = tid >> 5;
    const int lane = tid & 31;
    const int qr   = lane >> 2;
    const int qc   = lane & 3;
    const int bh   = blockIdx.y;
    const int q0   = blockIdx.x * 64;
    const int wr   = wid * 16;
    const int lr   = tid >> 4;          // loader row (+8*i)
    const int lc   = tid & 15;          // loader f4-col

    const float* Qg = g_qkv + (size_t)bh * SEQ * HD;
    const float* Kg = g_qkv + (size_t)(BATCH * NH + bh) * SEQ * HD;
    const float* Vg = g_qkv + (size_t)(2 * BATCH * NH + bh) * SEQ * HD;  // [d][s]

    // Stage Q (scaled) into Vh/Vl, then pull A-fragments into registers.
    #pragma unroll
    for (int i = 0; i < 8; i++) {
        int r = lr + 8 * i;
        float4 q = *(const float4*)(Qg + (size_t)(q0 + r) * HD + 4 * lc);
        unsigned h0, l0, h1, l1;
        split2(q.x * 0.125f, q.y * 0.125f, h0, l0);
        split2(q.z * 0.125f, q.w * 0.125f, h1, l1);
        *(uint2*)&Vh[r][2 * lc] = make_uint2(h0, h1);
        *(uint2*)&Vl[r][2 * lc] = make_uint2(l0, l1);
    }
    __syncthreads();

    unsigned qh[4][4], ql[4][4];
    #pragma unroll
    for (int kk = 0; kk < 4; kk++) {
        qh[kk][0] = Vh[wr + qr    ][kk * 8 + qc];
        qh[kk][1] = Vh[wr + qr + 8][kk * 8 + qc];
        qh[kk][2] = Vh[wr + qr    ][kk * 8 + qc + 4];
        qh[kk][3] = Vh[wr + qr + 8][kk * 8 + qc + 4];
        ql[kk][0] = Vl[wr + qr    ][kk * 8 + qc];
        ql[kk][1] = Vl[wr + qr + 8][kk * 8 + qc];
        ql[kk][2] = Vl[wr + qr    ][kk * 8 + qc + 4];
        ql[kk][3] = Vl[wr + qr + 8][kk * 8 + qc + 4];
    }

    float m0 = -1e30f, m1 = -1e30f, l0s = 0.f, l1s = 0.f;
    float O[8][4];
    #pragma unroll
    for (int j = 0; j < 8; j++)
        #pragma unroll
        for (int c = 0; c < 4; c++) O[j][c] = 0.f;

    for (int kv0 = 0; kv0 < SEQ; kv0 += 64) {
        __syncthreads();   // prev S/PV reads of Kh/Vh complete (also guards Q staging)
        #pragma unroll
        for (int i = 0; i < 8; i++) {
            int r = lr + 8 * i;
            float4 k = *(const float4*)(Kg + (size_t)(kv0 + r) * HD + 4 * lc);
            unsigned h0, l0, h1, l1;
            split2(k.x, k.y, h0, l0);
            split2(k.z, k.w, h1, l1);
            *(uint2*)&Kh[r][2 * lc] = make_uint2(h0, h1);
            *(uint2*)&Kl[r][2 * lc] = make_uint2(l0, l1);
        }
        #pragma unroll
        for (int i = 0; i < 8; i++) {
            int r = lr + 8 * i;   // r = d row; coalesced thanks to V^T layout
            float4 v = *(const float4*)(Vg + (size_t)r * SEQ + kv0 + 4 * lc);
            unsigned h0, l0, h1, l1;
            split2(v.x, v.y, h0, l0);
            split2(v.z, v.w, h1, l1);
            *(uint2*)&Vh[r][2 * lc] = make_uint2(h0, h1);
            *(uint2*)&Vl[r][2 * lc] = make_uint2(l0, l1);
        }
        __syncthreads();

        // S = Q K^T
        float S[8][4];
        #pragma unroll
        for (int j = 0; j < 8; j++)
            #pragma unroll
            for (int c = 0; c < 4; c++) S[j][c] = 0.f;

        #pragma unroll
        for (int kk = 0; kk < 4; kk++) {
            #pragma unroll
            for (int j = 0; j < 8; j++) {
                unsigned kbh[2], kbl[2];
                kbh[0] = Kh[j * 8 + qr][kk * 8 + qc];
                kbh[1] = Kh[j * 8 + qr][kk * 8 + qc + 4];
                kbl[0] = Kl[j * 8 + qr][kk * 8 + qc];
                kbl[1] = Kl[j * 8 + qr][kk * 8 + qc + 4];
                mma_bf16(S[j], qh[kk], kbh);
                mma_bf16(S[j], qh[kk], kbl);
                mma_bf16(S[j], ql[kk], kbh);
            }
        }

        // Online softmax (rows qr, qr+8; quad shuffles span the 64 cols)
        float mx0 = -1e30f, mx1 = -1e30f;
        #pragma unroll
        for (int j = 0; j < 8; j++) {
            mx0 = fmaxf(mx0, fmaxf(S[j][0], S[j][1]));
            mx1 = fmaxf(mx1, fmaxf(S[j][2], S[j][3]));
        }
        #pragma unroll
        for (int k = 1; k <= 2; k <<= 1) {
            mx0 = fmaxf(mx0, __shfl_xor_sync(0xffffffffu, mx0, k));
            mx1 = fmaxf(mx1, __shfl_xor_sync(0xffffffffu, mx1, k));
        }
        float nm0 = fmaxf(m0, mx0), nm1 = fmaxf(m1, mx1);
        float sc0 = __expf(m0 - nm0), sc1 = __expf(m1 - nm1);
        m0 = nm0; m1 = nm1;
        float s0 = 0.f, s1 = 0.f;
        #pragma unroll
        for (int j = 0; j < 8; j++) {
            S[j][0] = __expf(S[j][0] - nm0);
            S[j][1] = __expf(S[j][1] - nm0);
            S[j][2] = __expf(S[j][2] - nm1);
            S[j][3] = __expf(S[j][3] - nm1);
            s0 += S[j][0] + S[j][1];
            s1 += S[j][2] + S[j][3];
            O[j][0] *= sc0; O[j][1] *= sc0; O[j][2] *= sc1; O[j][3] *= sc1;
        }
        #pragma unroll
        for (int k = 1; k <= 2; k <<= 1) {
            s0 += __shfl_xor_sync(0xffffffffu, s0, k);
            s1 += __shfl_xor_sync(0xffffffffu, s1, k);
        }
        l0s = l0s * sc0 + s0;
        l1s = l1s * sc1 + s1;

        // O += P V : P comes straight from S registers (C-frag == A-frag)
        #pragma unroll
        for (int kk = 0; kk < 4; kk++) {
            unsigned ph[4], pl[4];
            split2(S[2 * kk    ][0], S[2 * kk    ][1], ph[0], pl[0]);
            split2(S[2 * kk    ][2], S[2 * kk    ][3], ph[1], pl[1]);
            split2(S[2 * kk + 1][0], S[2 * kk + 1][1], ph[2], pl[2]);
            split2(S[2 * kk + 1][2], S[2 * kk + 1][3], ph[3], pl[3]);
            #pragma unroll
            for (int j = 0; j < 8; j++) {
                unsigned vbh[2], vbl[2];
                vbh[0] = Vh[j * 8 + qr][kk * 8 + qc];
                vbh[1] = Vh[j * 8 + qr][kk * 8 + qc + 4];
                vbl[0] = Vl[j * 8 + qr][kk * 8 + qc];
                vbl[1] = Vl[j * 8 + qr][kk * 8 + qc + 4];
                mma_bf16(O[j], ph, vbh);
                mma_bf16(O[j], ph, vbl);
                mma_bf16(O[j], pl, vbh);
            }
        }
    }

    // Epilogue
    const int b = bh >> 4, h = bh & 15;
    const float inv0 = 1.f / l0s, inv1 = 1.f / l1s;
    const int rg0 = q0 + wr + qr;
    #pragma unroll
    for (int j = 0; j < 8; j++) {
        int col = h * HD + j * 8 + 2 * qc;
        *(float2*)(out + (size_t)(b * SEQ + rg0    ) * DM + col) =
            make_float2(O[j][0] * inv0, O[j][1] * inv0);
        *(float2*)(out + (size_t)(b * SEQ + rg0 + 8) * DM + col) =
            make_float2(O[j][2] * inv1, O[j][3] * inv1);
    }
}

extern "C" void kernel_launch(void* const* d_in, const int* in_sizes, int n_in,
                              void* d_out, int out_size)
{
    const float* X    = (const float*)d_in[0];
    const float* Wq   = (const float*)d_in[1];
    const float* Wk   = (const float*)d_in[2];
    const float* Wv   = (const float*)d_in[3];
    const float* sinT = (const float*)d_in[4];
    const float* cosT = (const float*)d_in[5];
    float* out = (float*)d_out;

    dim3 g1(DM / 64, (BATCH * SEQ) / 128, 3);
    qkv_gemm_rope<<<g1, 256>>>(X, Wq, Wk, Wv, sinT, cosT);

    dim3 g2(SEQ / 64, BATCH * NH);
    attn_kernel<<<g2, 128>>>(out);
}

// round 6
// speedup vs baseline: 3.6952x; 1.0896x over previous
#include <cuda_runtime.h>
#include <cuda_bf16.h>

#define SEQ    2048
#define DM     1024
#define NH     16
#define HD     64
#define BATCH  2

#define PLANE ((size_t)BATCH * NH * SEQ * HD)

// Persistent bf16 hi/lo planes, written by the GEMM, read by attention.
// Q/K: [bh][s][d].  V: transposed [bh][d][s].
__device__ __nv_bfloat16 g_qh[PLANE], g_ql[PLANE];
__device__ __nv_bfloat16 g_kh[PLANE], g_kl[PLANE];
__device__ __nv_bfloat16 g_vh[PLANE], g_vl[PLANE];

// ---------------------------------------------------------------------------
// Helpers
// ---------------------------------------------------------------------------
__device__ __forceinline__ void split2(float x, float y, unsigned& hi, unsigned& lo) {
    __nv_bfloat162 h = __float22bfloat162_rn(make_float2(x, y));
    float hx = __bfloat162float(__low2bfloat16(h));
    float hy = __bfloat162float(__high2bfloat16(h));
    __nv_bfloat162 l = __float22bfloat162_rn(make_float2(x - hx, y - hy));
    hi = *reinterpret_cast<unsigned*>(&h);
    lo = *reinterpret_cast<unsigned*>(&l);
}
__device__ __forceinline__ void mma_bf16(float d[4], const unsigned a[4], const unsigned b[2]) {
    asm volatile(
        "mma.sync.aligned.m16n8k16.row.col.f32.bf16.bf16.f32 "
        "{%0,%1,%2,%3},{%4,%5,%6,%7},{%8,%9},{%0,%1,%2,%3};\n"
        : "+f"(d[0]), "+f"(d[1]), "+f"(d[2]), "+f"(d[3])
        : "r"(a[0]), "r"(a[1]), "r"(a[2]), "r"(a[3]), "r"(b[0]), "r"(b[1]));
}
__device__ __forceinline__ void cpa16(unsigned dst, const void* src) {
    asm volatile("cp.async.cg.shared.global [%0], [%1], 16;\n"
                 :: "r"(dst), "l"(src));
}

// ---------------------------------------------------------------------------
// Kernel A: Y = X @ W (3 mats), RoPE fused, split to bf16 hi/lo planes.
// Tile 128x64, BK=32, 256 thr. Grid (16, 32, 3).
// ---------------------------------------------------------------------------
__global__ __launch_bounds__(256) void qkv_gemm_rope(
    const float* __restrict__ X,
    const float* __restrict__ Wq,
    const float* __restrict__ Wk,
    const float* __restrict__ Wv,
    const float* __restrict__ sinT,
    const float* __restrict__ cosT)
{
    const int mat = blockIdx.z;
    const float* W = (mat == 0) ? Wq : (mat == 1) ? Wk : Wv;

    __shared__ unsigned Ah[128][20], Al[128][20];
    __shared__ unsigned Bh[64][20],  Bl[64][20];

    const int tid  = threadIdx.x;
    const int wid  = tid >> 5;
    const int lane = tid & 31;
    const int wm   = wid >> 1;
    const int wn   = wid & 1;
    const int qr   = lane >> 2;
    const int qc   = lane & 3;
    const int row0 = blockIdx.y * 128;
    const int col0 = blockIdx.x * 64;

    const int ar  = tid >> 3;
    const int ac  = tid & 7;
    const int bc  = tid & 15;
    const int bk2 = tid >> 4;
    const int bsw = bk2 ^ (2 * (bc & 7));

    float4 xa[4], wb0, wb1;

    float acc[2][4][4];
    #pragma unroll
    for (int mi = 0; mi < 2; mi++)
        #pragma unroll
        for (int j = 0; j < 4; j++)
            #pragma unroll
            for (int c = 0; c < 4; c++) acc[mi][j][c] = 0.f;

    #pragma unroll
    for (int i = 0; i < 4; i++)
        xa[i] = *(const float4*)(X + (size_t)(row0 + ar + 32 * i) * DM + 4 * ac);
    wb0 = *(const float4*)(W + (size_t)(2 * bk2) * DM + col0 + 4 * bc);
    wb1 = *(const float4*)(W + (size_t)(2 * bk2 + 1) * DM + col0 + 4 * bc);

    for (int k0 = 0; k0 < DM; k0 += 32) {
        #pragma unroll
        for (int i = 0; i < 4; i++) {
            int r = ar + 32 * i;
            unsigned h0, l0, h1, l1;
            split2(xa[i].x, xa[i].y, h0, l0);
            split2(xa[i].z, xa[i].w, h1, l1);
            *(uint2*)&Ah[r][2 * ac] = make_uint2(h0, h1);
            *(uint2*)&Al[r][2 * ac] = make_uint2(l0, l1);
        }
        {
            const float* w0 = (const float*)&wb0;
            const float* w1 = (const float*)&wb1;
            #pragma unroll
            for (int j = 0; j < 4; j++) {
                unsigned h, l;
                split2(w0[j], w1[j], h, l);
                Bh[4 * bc + j][bsw] = h;
                Bl[4 * bc + j][bsw] = l;
            }
        }
        __syncthreads();

        if (k0 + 32 < DM) {
            #pragma unroll
            for (int i = 0; i < 4; i++)
                xa[i] = *(const float4*)(X + (size_t)(row0 + ar + 32 * i) * DM + k0 + 32 + 4 * ac);
            wb0 = *(const float4*)(W + (size_t)(k0 + 32 + 2 * bk2) * DM + col0 + 4 * bc);
            wb1 = *(const float4*)(W + (size_t)(k0 + 32 + 2 * bk2 + 1) * DM + col0 + 4 * bc);
        }

        #pragma unroll
        for (int ks = 0; ks < 2; ks++) {
            unsigned ah[2][4], al[2][4];
            #pragma unroll
            for (int mi = 0; mi < 2; mi++) {
                int rb = wm * 32 + mi * 16;
                ah[mi][0] = Ah[rb + qr    ][ks * 8 + qc];
                ah[mi][1] = Ah[rb + qr + 8][ks * 8 + qc];
                ah[mi][2] = Ah[rb + qr    ][ks * 8 + qc + 4];
                ah[mi][3] = Ah[rb + qr + 8][ks * 8 + qc + 4];
                al[mi][0] = Al[rb + qr    ][ks * 8 + qc];
                al[mi][1] = Al[rb + qr + 8][ks * 8 + qc];
                al[mi][2] = Al[rb + qr    ][ks * 8 + qc + 4];
                al[mi][3] = Al[rb + qr + 8][ks * 8 + qc + 4];
            }
            #pragma unroll
            for (int j = 0; j < 4; j++) {
                const int nb = wn * 32 + j * 8;
                const int sw = 2 * (((nb >> 2) + (qr >> 2)) & 7);
                unsigned bh[2], bl[2];
                bh[0] = Bh[nb + qr][(ks * 8 + qc    ) ^ sw];
                bh[1] = Bh[nb + qr][(ks * 8 + qc + 4) ^ sw];
                bl[0] = Bl[nb + qr][(ks * 8 + qc    ) ^ sw];
                bl[1] = Bl[nb + qr][(ks * 8 + qc + 4) ^ sw];
                mma_bf16(acc[0][j], ah[0], bh);
                mma_bf16(acc[0][j], ah[0], bl);
                mma_bf16(acc[0][j], al[0], bh);
                mma_bf16(acc[1][j], ah[1], bh);
                mma_bf16(acc[1][j], ah[1], bl);
                mma_bf16(acc[1][j], al[1], bh);
            }
        }
        __syncthreads();
    }

    // Epilogue: RoPE -> split -> bf16 plane scatter.
    const int h = blockIdx.x;
    #pragma unroll
    for (int mi = 0; mi < 2; mi++) {
        #pragma unroll
        for (int half = 0; half < 2; half++) {
            int rg = row0 + wm * 32 + mi * 16 + qr + half * 8;
            int s  = rg & (SEQ - 1);
            int b  = rg >> 11;
            const size_t hb = (size_t)(b * NH + h) * SEQ * HD;
            #pragma unroll
            for (int j = 0; j < 4; j++) {
                float x1 = acc[mi][j][half * 2 + 0];
                float x2 = acc[mi][j][half * 2 + 1];
                int hd = wn * 32 + j * 8 + 2 * qc;
                int pi = hd >> 1;
                float sn = sinT[s * (HD / 2) + pi];
                float cs = cosT[s * (HD / 2) + pi];
                float o1 = x1 * cs - x2 * sn;
                float o2 = x2 * cs + x1 * sn;
                if (mat == 0) { o1 *= 0.125f; o2 *= 0.125f; }   // pre-scale Q
                unsigned hh, ll;
                split2(o1, o2, hh, ll);
                if (mat == 2) {
                    __nv_bfloat162 hv = *reinterpret_cast<__nv_bfloat162*>(&hh);
                    __nv_bfloat162 lv = *reinterpret_cast<__nv_bfloat162*>(&ll);
                    g_vh[hb + (size_t)hd * SEQ + s]       = __low2bfloat16(hv);
                    g_vh[hb + (size_t)(hd + 1) * SEQ + s] = __high2bfloat16(hv);
                    g_vl[hb + (size_t)hd * SEQ + s]       = __low2bfloat16(lv);
                    g_vl[hb + (size_t)(hd + 1) * SEQ + s] = __high2bfloat16(lv);
                } else {
                    __nv_bfloat16* ph = (mat == 0) ? g_qh : g_kh;
                    __nv_bfloat16* pl = (mat == 0) ? g_ql : g_kl;
                    *(unsigned*)&ph[hb + (size_t)s * HD + hd] = hh;
                    *(unsigned*)&pl[hb + (size_t)s * HD + hd] = ll;
                }
            }
        }
    }
}

// ---------------------------------------------------------------------------
// Kernel B: flash attention. Pure cp.async + LDS + MMA mainloop.
// 128 thr (4 warps), q-tile 64, target 4 blocks/SM. Grid (SEQ/64, B*NH).
// ---------------------------------------------------------------------------
__global__ __launch_bounds__(128, 4) void attn_kernel(float* __restrict__ out)
{
    __shared__ __nv_bfloat16 sKh[64][72], sKl[64][72];   // [kv][d]
    __shared__ __nv_bfloat16 sVh[64][72], sVl[64][72];   // [d][kv]

    const int tid  = threadIdx.x;
    const int wid  = tid >> 5;
    const int lane = tid & 31;
    const int qr   = lane >> 2;
    const int qc   = lane & 3;
    const int bh   = blockIdx.y;
    const int q0   = blockIdx.x * 64;
    const int wr   = wid * 16;
    const int lrow = tid >> 3;          // loader row (+16*i)
    const int lch  = tid & 7;           // 16B chunk within 128B row

    const size_t hb = (size_t)bh * SEQ * HD;
    const __nv_bfloat16* Kh = g_kh + hb;
    const __nv_bfloat16* Kl = g_kl + hb;
    const __nv_bfloat16* Vh = g_vh + hb;
    const __nv_bfloat16* Vl = g_vl + hb;

    const unsigned sKhB = (unsigned)__cvta_generic_to_shared(&sKh[0][0]);
    const unsigned sKlB = (unsigned)__cvta_generic_to_shared(&sKl[0][0]);
    const unsigned sVhB = (unsigned)__cvta_generic_to_shared(&sVh[0][0]);
    const unsigned sVlB = (unsigned)__cvta_generic_to_shared(&sVl[0][0]);

    // Q fragments straight from global (hi/lo planes, 32-bit words).
    unsigned fqh[4][4], fql[4][4];
    {
        const unsigned* qwh = (const unsigned*)(g_qh + hb);
        const unsigned* qwl = (const unsigned*)(g_ql + hb);
        const int r0 = (q0 + wr + qr) * (HD / 2);
        const int r1 = r0 + 8 * (HD / 2);
        #pragma unroll
        for (int kk = 0; kk < 4; kk++) {
            fqh[kk][0] = qwh[r0 + kk * 8 + qc];
            fqh[kk][1] = qwh[r1 + kk * 8 + qc];
            fqh[kk][2] = qwh[r0 + kk * 8 + qc + 4];
            fqh[kk][3] = qwh[r1 + kk * 8 + qc + 4];
            fql[kk][0] = qwl[r0 + kk * 8 + qc];
            fql[kk][1] = qwl[r1 + kk * 8 + qc];
            fql[kk][2] = qwl[r0 + kk * 8 + qc + 4];
            fql[kk][3] = qwl[r1 + kk * 8 + qc + 4];
        }
    }

    float m0 = -1e30f, m1 = -1e30f, l0s = 0.f, l1s = 0.f;
    float O[8][4];
    #pragma unroll
    for (int j = 0; j < 8; j++)
        #pragma unroll
        for (int c = 0; c < 4; c++) O[j][c] = 0.f;

    const unsigned* Khw = (const unsigned*)&sKh[0][0];
    const unsigned* Klw = (const unsigned*)&sKl[0][0];
    const unsigned* Vhw = (const unsigned*)&sVh[0][0];
    const unsigned* Vlw = (const unsigned*)&sVl[0][0];

    for (int kv0 = 0; kv0 < SEQ; kv0 += 64) {
        if (kv0) __syncthreads();       // prior tile reads complete
        #pragma unroll
        for (int i = 0; i < 4; i++) {
            const int r = lrow + 16 * i;
            const unsigned so = r * 144 + lch * 16;
            cpa16(sKhB + so, Kh + (size_t)(kv0 + r) * HD + lch * 8);
            cpa16(sKlB + so, Kl + (size_t)(kv0 + r) * HD + lch * 8);
            cpa16(sVhB + so, Vh + (size_t)r * SEQ + kv0 + lch * 8);
            cpa16(sVlB + so, Vl + (size_t)r * SEQ + kv0 + lch * 8);
        }
        asm volatile("cp.async.commit_group;\n" ::: "memory");
        asm volatile("cp.async.wait_group 0;\n" ::: "memory");
        __syncthreads();

        // S = Q K^T
        float S[8][4];
        #pragma unroll
        for (int j = 0; j < 8; j++)
            #pragma unroll
            for (int c = 0; c < 4; c++) S[j][c] = 0.f;

        #pragma unroll
        for (int kk = 0; kk < 4; kk++) {
            #pragma unroll
            for (int j = 0; j < 8; j++) {
                const int rw = (j * 8 + qr) * 36 + kk * 8 + qc;
                unsigned kbh[2], kbl[2];
                kbh[0] = Khw[rw];
                kbh[1] = Khw[rw + 4];
                kbl[0] = Klw[rw];
                kbl[1] = Klw[rw + 4];
                mma_bf16(S[j], fqh[kk], kbh);
                mma_bf16(S[j], fqh[kk], kbl);
                mma_bf16(S[j], fql[kk], kbh);
            }
        }

        // Online softmax (rows qr, qr+8)
        float mx0 = -1e30f, mx1 = -1e30f;
        #pragma unroll
        for (int j = 0; j < 8; j++) {
            mx0 = fmaxf(mx0, fmaxf(S[j][0], S[j][1]));
            mx1 = fmaxf(mx1, fmaxf(S[j][2], S[j][3]));
        }
        #pragma unroll
        for (int k = 1; k <= 2; k <<= 1) {
            mx0 = fmaxf(mx0, __shfl_xor_sync(0xffffffffu, mx0, k));
            mx1 = fmaxf(mx1, __shfl_xor_sync(0xffffffffu, mx1, k));
        }
        float nm0 = fmaxf(m0, mx0), nm1 = fmaxf(m1, mx1);
        float sc0 = __expf(m0 - nm0), sc1 = __expf(m1 - nm1);
        m0 = nm0; m1 = nm1;
        float s0 = 0.f, s1 = 0.f;
        #pragma unroll
        for (int j = 0; j < 8; j++) {
            S[j][0] = __expf(S[j][0] - nm0);
            S[j][1] = __expf(S[j][1] - nm0);
            S[j][2] = __expf(S[j][2] - nm1);
            S[j][3] = __expf(S[j][3] - nm1);
            s0 += S[j][0] + S[j][1];
            s1 += S[j][2] + S[j][3];
            O[j][0] *= sc0; O[j][1] *= sc0; O[j][2] *= sc1; O[j][3] *= sc1;
        }
        #pragma unroll
        for (int k = 1; k <= 2; k <<= 1) {
            s0 += __shfl_xor_sync(0xffffffffu, s0, k);
            s1 += __shfl_xor_sync(0xffffffffu, s1, k);
        }
        l0s = l0s * sc0 + s0;
        l1s = l1s * sc1 + s1;

        // O += P V  (P from S registers; C-frag == A-frag layout)
        #pragma unroll
        for (int kk = 0; kk < 4; kk++) {
            unsigned ph[4], pl[4];
            split2(S[2 * kk    ][0], S[2 * kk    ][1], ph[0], pl[0]);
            split2(S[2 * kk    ][2], S[2 * kk    ][3], ph[1], pl[1]);
            split2(S[2 * kk + 1][0], S[2 * kk + 1][1], ph[2], pl[2]);
            split2(S[2 * kk + 1][2], S[2 * kk + 1][3], ph[3], pl[3]);
            #pragma unroll
            for (int j = 0; j < 8; j++) {
                const int rw = (j * 8 + qr) * 36 + kk * 8 + qc;
                unsigned vbh[2], vbl[2];
                vbh[0] = Vhw[rw];
                vbh[1] = Vhw[rw + 4];
                vbl[0] = Vlw[rw];
                vbl[1] = Vlw[rw + 4];
                mma_bf16(O[j], ph, vbh);
                mma_bf16(O[j], ph, vbl);
                mma_bf16(O[j], pl, vbh);
            }
        }
    }

    // Epilogue
    const int b = bh >> 4, h = bh & 15;
    const float inv0 = 1.f / l0s, inv1 = 1.f / l1s;
    const int rg0 = q0 + wr + qr;
    #pragma unroll
    for (int j = 0; j < 8; j++) {
        int col = h * HD + j * 8 + 2 * qc;
        *(float2*)(out + (size_t)(b * SEQ + rg0    ) * DM + col) =
            make_float2(O[j][0] * inv0, O[j][1] * inv0);
        *(float2*)(out + (size_t)(b * SEQ + rg0 + 8) * DM + col) =
            make_float2(O[j][2] * inv1, O[j][3] * inv1);
    }
}

extern "C" void kernel_launch(void* const* d_in, const int* in_sizes, int n_in,
                              void* d_out, int out_size)
{
    const float* X    = (const float*)d_in[0];
    const float* Wq   = (const float*)d_in[1];
    const float* Wk   = (const float*)d_in[2];
    const float* Wv   = (const float*)d_in[3];
    const float* sinT = (const float*)d_in[4];
    const float* cosT = (const float*)d_in[5];
    float* out = (float*)d_out;

    dim3 g1(DM / 64, (BATCH * SEQ) / 128, 3);
    qkv_gemm_rope<<<g1, 256>>>(X, Wq, Wk, Wv, sinT, cosT);

    dim3 g2(SEQ / 64, BATCH * NH);
    attn_kernel<<<g2, 128>>>(out);
}

// round 7
// speedup vs baseline: 3.7051x; 1.0027x over previous
#include <cuda_runtime.h>
#include <cuda_bf16.h>

#define SEQ    2048
#define DM     1024
#define NH     16
#define HD     64
#define BATCH  2

#define PLANE ((size_t)BATCH * NH * SEQ * HD)

// Persistent bf16 hi/lo planes, written by the GEMM, read by attention.
// Q/K: [bh][s][d].  V: transposed [bh][d][s].
__device__ __nv_bfloat16 g_qh[PLANE], g_ql[PLANE];
__device__ __nv_bfloat16 g_kh[PLANE], g_kl[PLANE];
__device__ __nv_bfloat16 g_vh[PLANE], g_vl[PLANE];

// ---------------------------------------------------------------------------
// Helpers
// ---------------------------------------------------------------------------
__device__ __forceinline__ void split2(float x, float y, unsigned& hi, unsigned& lo) {
    __nv_bfloat162 h = __float22bfloat162_rn(make_float2(x, y));
    float hx = __bfloat162float(__low2bfloat16(h));
    float hy = __bfloat162float(__high2bfloat16(h));
    __nv_bfloat162 l = __float22bfloat162_rn(make_float2(x - hx, y - hy));
    hi = *reinterpret_cast<unsigned*>(&h);
    lo = *reinterpret_cast<unsigned*>(&l);
}
__device__ __forceinline__ void mma_bf16(float d[4], const unsigned a[4], const unsigned b[2]) {
    asm volatile(
        "mma.sync.aligned.m16n8k16.row.col.f32.bf16.bf16.f32 "
        "{%0,%1,%2,%3},{%4,%5,%6,%7},{%8,%9},{%0,%1,%2,%3};\n"
        : "+f"(d[0]), "+f"(d[1]), "+f"(d[2]), "+f"(d[3])
        : "r"(a[0]), "r"(a[1]), "r"(a[2]), "r"(a[3]), "r"(b[0]), "r"(b[1]));
}
__device__ __forceinline__ void cpa16(unsigned dst, const void* src) {
    asm volatile("cp.async.cg.shared.global [%0], [%1], 16;\n"
                 :: "r"(dst), "l"(src));
}

// ---------------------------------------------------------------------------
// Kernel A: Y = X @ W (3 mats), RoPE fused, split to bf16 hi/lo planes.
// Tile 128x64, BK=32, 256 thr. Grid (16, 32, 3).  (unchanged from R6)
// ---------------------------------------------------------------------------
__global__ __launch_bounds__(256) void qkv_gemm_rope(
    const float* __restrict__ X,
    const float* __restrict__ Wq,
    const float* __restrict__ Wk,
    const float* __restrict__ Wv,
    const float* __restrict__ sinT,
    const float* __restrict__ cosT)
{
    const int mat = blockIdx.z;
    const float* W = (mat == 0) ? Wq : (mat == 1) ? Wk : Wv;

    __shared__ unsigned Ah[128][20], Al[128][20];
    __shared__ unsigned Bh[64][20],  Bl[64][20];

    const int tid  = threadIdx.x;
    const int wid  = tid >> 5;
    const int lane = tid & 31;
    const int wm   = wid >> 1;
    const int wn   = wid & 1;
    const int qr   = lane >> 2;
    const int qc   = lane & 3;
    const int row0 = blockIdx.y * 128;
    const int col0 = blockIdx.x * 64;

    const int ar  = tid >> 3;
    const int ac  = tid & 7;
    const int bc  = tid & 15;
    const int bk2 = tid >> 4;
    const int bsw = bk2 ^ (2 * (bc & 7));

    float4 xa[4], wb0, wb1;

    float acc[2][4][4];
    #pragma unroll
    for (int mi = 0; mi < 2; mi++)
        #pragma unroll
        for (int j = 0; j < 4; j++)
            #pragma unroll
            for (int c = 0; c < 4; c++) acc[mi][j][c] = 0.f;

    #pragma unroll
    for (int i = 0; i < 4; i++)
        xa[i] = *(const float4*)(X + (size_t)(row0 + ar + 32 * i) * DM + 4 * ac);
    wb0 = *(const float4*)(W + (size_t)(2 * bk2) * DM + col0 + 4 * bc);
    wb1 = *(const float4*)(W + (size_t)(2 * bk2 + 1) * DM + col0 + 4 * bc);

    for (int k0 = 0; k0 < DM; k0 += 32) {
        #pragma unroll
        for (int i = 0; i < 4; i++) {
            int r = ar + 32 * i;
            unsigned h0, l0, h1, l1;
            split2(xa[i].x, xa[i].y, h0, l0);
            split2(xa[i].z, xa[i].w, h1, l1);
            *(uint2*)&Ah[r][2 * ac] = make_uint2(h0, h1);
            *(uint2*)&Al[r][2 * ac] = make_uint2(l0, l1);
        }
        {
            const float* w0 = (const float*)&wb0;
            const float* w1 = (const float*)&wb1;
            #pragma unroll
            for (int j = 0; j < 4; j++) {
                unsigned h, l;
                split2(w0[j], w1[j], h, l);
                Bh[4 * bc + j][bsw] = h;
                Bl[4 * bc + j][bsw] = l;
            }
        }
        __syncthreads();

        if (k0 + 32 < DM) {
            #pragma unroll
            for (int i = 0; i < 4; i++)
                xa[i] = *(const float4*)(X + (size_t)(row0 + ar + 32 * i) * DM + k0 + 32 + 4 * ac);
            wb0 = *(const float4*)(W + (size_t)(k0 + 32 + 2 * bk2) * DM + col0 + 4 * bc);
            wb1 = *(const float4*)(W + (size_t)(k0 + 32 + 2 * bk2 + 1) * DM + col0 + 4 * bc);
        }

        #pragma unroll
        for (int ks = 0; ks < 2; ks++) {
            unsigned ah[2][4], al[2][4];
            #pragma unroll
            for (int mi = 0; mi < 2; mi++) {
                int rb = wm * 32 + mi * 16;
                ah[mi][0] = Ah[rb + qr    ][ks * 8 + qc];
                ah[mi][1] = Ah[rb + qr + 8][ks * 8 + qc];
                ah[mi][2] = Ah[rb + qr    ][ks * 8 + qc + 4];
                ah[mi][3] = Ah[rb + qr + 8][ks * 8 + qc + 4];
                al[mi][0] = Al[rb + qr    ][ks * 8 + qc];
                al[mi][1] = Al[rb + qr + 8][ks * 8 + qc];
                al[mi][2] = Al[rb + qr    ][ks * 8 + qc + 4];
                al[mi][3] = Al[rb + qr + 8][ks * 8 + qc + 4];
            }
            #pragma unroll
            for (int j = 0; j < 4; j++) {
                const int nb = wn * 32 + j * 8;
                const int sw = 2 * (((nb >> 2) + (qr >> 2)) & 7);
                unsigned bh[2], bl[2];
                bh[0] = Bh[nb + qr][(ks * 8 + qc    ) ^ sw];
                bh[1] = Bh[nb + qr][(ks * 8 + qc + 4) ^ sw];
                bl[0] = Bl[nb + qr][(ks * 8 + qc    ) ^ sw];
                bl[1] = Bl[nb + qr][(ks * 8 + qc + 4) ^ sw];
                mma_bf16(acc[0][j], ah[0], bh);
                mma_bf16(acc[0][j], ah[0], bl);
                mma_bf16(acc[0][j], al[0], bh);
                mma_bf16(acc[1][j], ah[1], bh);
                mma_bf16(acc[1][j], ah[1], bl);
                mma_bf16(acc[1][j], al[1], bh);
            }
        }
        __syncthreads();
    }

    // Epilogue: RoPE -> split -> bf16 plane scatter.
    const int h = blockIdx.x;
    #pragma unroll
    for (int mi = 0; mi < 2; mi++) {
        #pragma unroll
        for (int half = 0; half < 2; half++) {
            int rg = row0 + wm * 32 + mi * 16 + qr + half * 8;
            int s  = rg & (SEQ - 1);
            int b  = rg >> 11;
            const size_t hb = (size_t)(b * NH + h) * SEQ * HD;
            #pragma unroll
            for (int j = 0; j < 4; j++) {
                float x1 = acc[mi][j][half * 2 + 0];
                float x2 = acc[mi][j][half * 2 + 1];
                int hd = wn * 32 + j * 8 + 2 * qc;
                int pi = hd >> 1;
                float sn = sinT[s * (HD / 2) + pi];
                float cs = cosT[s * (HD / 2) + pi];
                float o1 = x1 * cs - x2 * sn;
                float o2 = x2 * cs + x1 * sn;
                if (mat == 0) { o1 *= 0.125f; o2 *= 0.125f; }   // pre-scale Q
                unsigned hh, ll;
                split2(o1, o2, hh, ll);
                if (mat == 2) {
                    __nv_bfloat162 hv = *reinterpret_cast<__nv_bfloat162*>(&hh);
                    __nv_bfloat162 lv = *reinterpret_cast<__nv_bfloat162*>(&ll);
                    g_vh[hb + (size_t)hd * SEQ + s]       = __low2bfloat16(hv);
                    g_vh[hb + (size_t)(hd + 1) * SEQ + s] = __high2bfloat16(hv);
                    g_vl[hb + (size_t)hd * SEQ + s]       = __low2bfloat16(lv);
                    g_vl[hb + (size_t)(hd + 1) * SEQ + s] = __high2bfloat16(lv);
                } else {
                    __nv_bfloat16* ph = (mat == 0) ? g_qh : g_kh;
                    __nv_bfloat16* pl = (mat == 0) ? g_ql : g_kl;
                    *(unsigned*)&ph[hb + (size_t)s * HD + hd] = hh;
                    *(unsigned*)&pl[hb + (size_t)s * HD + hd] = ll;
                }
            }
        }
    }
}

// ---------------------------------------------------------------------------
// Kernel B: flash attention, 256 thr (8 warps), q-tile 128, kv-tile 64,
// 2-stage cp.async pipeline, XOR-swizzled pad-free tiles (64KB dyn smem).
// Grid (SEQ/128, B*NH).
// ---------------------------------------------------------------------------
#define PBYTES 8192           // one 64x64 bf16 plane
#define STBYTES (4 * PBYTES)  // 4 planes per stage

extern __shared__ char dynsm[];

__global__ __launch_bounds__(256, 2) void attn_kernel(float* __restrict__ out)
{
    const int tid  = threadIdx.x;
    const int wid  = tid >> 5;
    const int lane = tid & 31;
    const int qr   = lane >> 2;
    const int qc   = lane & 3;
    const int bh   = blockIdx.y;
    const int q0   = blockIdx.x * 128;
    const int wr   = wid * 16;
    const int lrow = tid >> 3;          // loader row (+32*i)
    const int lch  = tid & 7;           // 16B chunk within 128B row

    const size_t hb = (size_t)bh * SEQ * HD;
    const __nv_bfloat16* Kh = g_kh + hb;
    const __nv_bfloat16* Kl = g_kl + hb;
    const __nv_bfloat16* Vh = g_vh + hb;
    const __nv_bfloat16* Vl = g_vl + hb;

    const unsigned sBase = (unsigned)__cvta_generic_to_shared(dynsm);

    // Q fragments straight from global (hi/lo planes, 32-bit words).
    unsigned fqh[4][4], fql[4][4];
    {
        const unsigned* qwh = (const unsigned*)(g_qh + hb);
        const unsigned* qwl = (const unsigned*)(g_ql + hb);
        const int r0 = (q0 + wr + qr) * (HD / 2);
        const int r1 = r0 + 8 * (HD / 2);
        #pragma unroll
        for (int kk = 0; kk < 4; kk++) {
            fqh[kk][0] = qwh[r0 + kk * 8 + qc];
            fqh[kk][1] = qwh[r1 + kk * 8 + qc];
            fqh[kk][2] = qwh[r0 + kk * 8 + qc + 4];
            fqh[kk][3] = qwh[r1 + kk * 8 + qc + 4];
            fql[kk][0] = qwl[r0 + kk * 8 + qc];
            fql[kk][1] = qwl[r1 + kk * 8 + qc];
            fql[kk][2] = qwl[r0 + kk * 8 + qc + 4];
            fql[kk][3] = qwl[r1 + kk * 8 + qc + 4];
        }
    }

    float m0 = -1e30f, m1 = -1e30f, l0s = 0.f, l1s = 0.f;
    float O[8][4];
    #pragma unroll
    for (int j = 0; j < 8; j++)
        #pragma unroll
        for (int c = 0; c < 4; c++) O[j][c] = 0.f;

    // Tile loader: stage st <- kv tile at kv0. XOR swizzle chunk^(row&7).
    auto issue_tile = [&](int st, int kv0) {
        const unsigned base = sBase + st * STBYTES;
        #pragma unroll
        for (int i = 0; i < 2; i++) {
            const int r = lrow + 32 * i;
            const unsigned so = r * 128 + ((lch ^ (r & 7)) * 16);
            cpa16(base + 0 * PBYTES + so, Kh + (size_t)(kv0 + r) * HD + lch * 8);
            cpa16(base + 1 * PBYTES + so, Kl + (size_t)(kv0 + r) * HD + lch * 8);
            cpa16(base + 2 * PBYTES + so, Vh + (size_t)r * SEQ + kv0 + lch * 8);
            cpa16(base + 3 * PBYTES + so, Vl + (size_t)r * SEQ + kv0 + lch * 8);
        }
        asm volatile("cp.async.commit_group;\n" ::: "memory");
    };

    const int T = SEQ / 64;
    issue_tile(0, 0);
    issue_tile(1, 64);

    for (int t = 0; t < T; t++) {
        if (t + 1 < T) asm volatile("cp.async.wait_group 1;\n" ::: "memory");
        else           asm volatile("cp.async.wait_group 0;\n" ::: "memory");
        __syncthreads();

        const unsigned* Khw = (const unsigned*)(dynsm + (t & 1) * STBYTES);
        const unsigned* Klw = Khw + PBYTES / 4;
        const unsigned* Vhw = Khw + 2 * (PBYTES / 4);
        const unsigned* Vlw = Khw + 3 * (PBYTES / 4);

        // S = Q K^T
        float S[8][4];
        #pragma unroll
        for (int j = 0; j < 8; j++)
            #pragma unroll
            for (int c = 0; c < 4; c++) S[j][c] = 0.f;

        #pragma unroll
        for (int kk = 0; kk < 4; kk++) {
            const int c0 = ((2 * kk    ) ^ qr) * 4 + qc;
            const int c1 = ((2 * kk + 1) ^ qr) * 4 + qc;
            #pragma unroll
            for (int j = 0; j < 8; j++) {
                const int rb = (j * 8 + qr) * 32;
                unsigned kbh[2], kbl[2];
                kbh[0] = Khw[rb + c0];
                kbh[1] = Khw[rb + c1];
                kbl[0] = Klw[rb + c0];
                kbl[1] = Klw[rb + c1];
                mma_bf16(S[j], fqh[kk], kbh);
                mma_bf16(S[j], fqh[kk], kbl);
                mma_bf16(S[j], fql[kk], kbh);
            }
        }

        // Online softmax (rows qr, qr+8)
        float mx0 = -1e30f, mx1 = -1e30f;
        #pragma unroll
        for (int j = 0; j < 8; j++) {
            mx0 = fmaxf(mx0, fmaxf(S[j][0], S[j][1]));
            mx1 = fmaxf(mx1, fmaxf(S[j][2], S[j][3]));
        }
        #pragma unroll
        for (int k = 1; k <= 2; k <<= 1) {
            mx0 = fmaxf(mx0, __shfl_xor_sync(0xffffffffu, mx0, k));
            mx1 = fmaxf(mx1, __shfl_xor_sync(0xffffffffu, mx1, k));
        }
        float nm0 = fmaxf(m0, mx0), nm1 = fmaxf(m1, mx1);
        float sc0 = __expf(m0 - nm0), sc1 = __expf(m1 - nm1);
        m0 = nm0; m1 = nm1;
        float s0 = 0.f, s1 = 0.f;
        #pragma unroll
        for (int j = 0; j < 8; j++) {
            S[j][0] = __expf(S[j][0] - nm0);
            S[j][1] = __expf(S[j][1] - nm0);
            S[j][2] = __expf(S[j][2] - nm1);
            S[j][3] = __expf(S[j][3] - nm1);
            s0 += S[j][0] + S[j][1];
            s1 += S[j][2] + S[j][3];
            O[j][0] *= sc0; O[j][1] *= sc0; O[j][2] *= sc1; O[j][3] *= sc1;
        }
        #pragma unroll
        for (int k = 1; k <= 2; k <<= 1) {
            s0 += __shfl_xor_sync(0xffffffffu, s0, k);
            s1 += __shfl_xor_sync(0xffffffffu, s1, k);
        }
        l0s = l0s * sc0 + s0;
        l1s = l1s * sc1 + s1;

        // O += P V  (P from S registers; C-frag == A-frag layout)
        #pragma unroll
        for (int kk = 0; kk < 4; kk++) {
            unsigned ph[4], pl[4];
            split2(S[2 * kk    ][0], S[2 * kk    ][1], ph[0], pl[0]);
            split2(S[2 * kk    ][2], S[2 * kk    ][3], ph[1], pl[1]);
            split2(S[2 * kk + 1][0], S[2 * kk + 1][1], ph[2], pl[2]);
            split2(S[2 * kk + 1][2], S[2 * kk + 1][3], ph[3], pl[3]);
            const int c0 = ((2 * kk    ) ^ qr) * 4 + qc;
            const int c1 = ((2 * kk + 1) ^ qr) * 4 + qc;
            #pragma unroll
            for (int j = 0; j < 8; j++) {
                const int rb = (j * 8 + qr) * 32;
                unsigned vbh[2], vbl[2];
                vbh[0] = Vhw[rb + c0];
                vbh[1] = Vhw[rb + c1];
                vbl[0] = Vlw[rb + c0];
                vbl[1] = Vlw[rb + c1];
                mma_bf16(O[j], ph, vbh);
                mma_bf16(O[j], ph, vbl);
                mma_bf16(O[j], pl, vbh);
            }
        }

        __syncthreads();                 // all reads of buffer (t&1) done
        if (t + 2 < T) issue_tile(t & 1, (t + 2) * 64);
    }

    // Epilogue
    const int b = bh >> 4, h = bh & 15;
    const float inv0 = 1.f / l0s, inv1 = 1.f / l1s;
    const int rg0 = q0 + wr + qr;
    #pragma unroll
    for (int j = 0; j < 8; j++) {
        int col = h * HD + j * 8 + 2 * qc;
        *(float2*)(out + (size_t)(b * SEQ + rg0    ) * DM + col) =
            make_float2(O[j][0] * inv0, O[j][1] * inv0);
        *(float2*)(out + (size_t)(b * SEQ + rg0 + 8) * DM + col) =
            make_float2(O[j][2] * inv1, O[j][3] * inv1);
    }
}

extern "C" void kernel_launch(void* const* d_in, const int* in_sizes, int n_in,
                              void* d_out, int out_size)
{
    const float* X    = (const float*)d_in[0];
    const float* Wq   = (const float*)d_in[1];
    const float* Wk   = (const float*)d_in[2];
    const float* Wv   = (const float*)d_in[3];
    const float* sinT = (const float*)d_in[4];
    const float* cosT = (const float*)d_in[5];
    float* out = (float*)d_out;

    cudaFuncSetAttribute(attn_kernel,
                         cudaFuncAttributeMaxDynamicSharedMemorySize,
                         2 * STBYTES);

    dim3 g1(DM / 64, (BATCH * SEQ) / 128, 3);
    qkv_gemm_rope<<<g1, 256>>>(X, Wq, Wk, Wv, sinT, cosT);

    dim3 g2(SEQ / 128, BATCH * NH);
    attn_kernel<<<g2, 256, 2 * STBYTES>>>(out);
}

// round 9
// speedup vs baseline: 3.8451x; 1.0378x over previous
#include <cuda_runtime.h>
#include <cuda_bf16.h>

#define SEQ    2048
#define DM     1024
#define NH     16
#define HD     64
#define BATCH  2

#define PLANE ((size_t)BATCH * NH * SEQ * HD)

// Persistent bf16 hi/lo planes, written by the GEMM, read by attention.
// Q/K: [bh][s][d].  V: transposed [bh][d][s].
__device__ __nv_bfloat16 g_qh[PLANE], g_ql[PLANE];
__device__ __nv_bfloat16 g_kh[PLANE], g_kl[PLANE];
__device__ __nv_bfloat16 g_vh[PLANE], g_vl[PLANE];

// ---------------------------------------------------------------------------
// Helpers
// ---------------------------------------------------------------------------
__device__ __forceinline__ void split2(float x, float y, unsigned& hi, unsigned& lo) {
    __nv_bfloat162 h = __float22bfloat162_rn(make_float2(x, y));
    float hx = __bfloat162float(__low2bfloat16(h));
    float hy = __bfloat162float(__high2bfloat16(h));
    __nv_bfloat162 l = __float22bfloat162_rn(make_float2(x - hx, y - hy));
    hi = *reinterpret_cast<unsigned*>(&h);
    lo = *reinterpret_cast<unsigned*>(&l);
}
__device__ __forceinline__ void mma_bf16(float d[4], const unsigned a[4], const unsigned b[2]) {
    asm volatile(
        "mma.sync.aligned.m16n8k16.row.col.f32.bf16.bf16.f32 "
        "{%0,%1,%2,%3},{%4,%5,%6,%7},{%8,%9},{%0,%1,%2,%3};\n"
        : "+f"(d[0]), "+f"(d[1]), "+f"(d[2]), "+f"(d[3])
        : "r"(a[0]), "r"(a[1]), "r"(a[2]), "r"(a[3]), "r"(b[0]), "r"(b[1]));
}
__device__ __forceinline__ void cpa16(unsigned dst, const void* src) {
    asm volatile("cp.async.cg.shared.global [%0], [%1], 16;\n"
                 :: "r"(dst), "l"(src));
}
__device__ __forceinline__ void ldsm4(unsigned& r0, unsigned& r1,
                                      unsigned& r2, unsigned& r3, unsigned addr) {
    asm volatile("ldmatrix.sync.aligned.m8n8.x4.shared.b16 {%0,%1,%2,%3}, [%4];\n"
                 : "=r"(r0), "=r"(r1), "=r"(r2), "=r"(r3) : "r"(addr));
}

// ---------------------------------------------------------------------------
// Kernel A: Y = X @ W (3 mats), RoPE fused, split to bf16 hi/lo planes.
// Tile 128x64, BK=32, 256 thr. Grid (16, 32, 3).  (unchanged — proven)
// ---------------------------------------------------------------------------
__global__ __launch_bounds__(256) void qkv_gemm_rope(
    const float* __restrict__ X,
    const float* __restrict__ Wq,
    const float* __restrict__ Wk,
    const float* __restrict__ Wv,
    const float* __restrict__ sinT,
    const float* __restrict__ cosT)
{
    const int mat = blockIdx.z;
    const float* W = (mat == 0) ? Wq : (mat == 1) ? Wk : Wv;

    __shared__ unsigned Ah[128][20], Al[128][20];
    __shared__ unsigned Bh[64][20],  Bl[64][20];

    const int tid  = threadIdx.x;
    const int wid  = tid >> 5;
    const int lane = tid & 31;
    const int wm   = wid >> 1;
    const int wn   = wid & 1;
    const int qr   = lane >> 2;
    const int qc   = lane & 3;
    const int row0 = blockIdx.y * 128;
    const int col0 = blockIdx.x * 64;

    const int ar  = tid >> 3;
    const int ac  = tid & 7;
    const int bc  = tid & 15;
    const int bk2 = tid >> 4;
    const int bsw = bk2 ^ (2 * (bc & 7));

    float4 xa[4], wb0, wb1;

    float acc[2][4][4];
    #pragma unroll
    for (int mi = 0; mi < 2; mi++)
        #pragma unroll
        for (int j = 0; j < 4; j++)
            #pragma unroll
            for (int c = 0; c < 4; c++) acc[mi][j][c] = 0.f;

    #pragma unroll
    for (int i = 0; i < 4; i++)
        xa[i] = *(const float4*)(X + (size_t)(row0 + ar + 32 * i) * DM + 4 * ac);
    wb0 = *(const float4*)(W + (size_t)(2 * bk2) * DM + col0 + 4 * bc);
    wb1 = *(const float4*)(W + (size_t)(2 * bk2 + 1) * DM + col0 + 4 * bc);

    for (int k0 = 0; k0 < DM; k0 += 32) {
        #pragma unroll
        for (int i = 0; i < 4; i++) {
            int r = ar + 32 * i;
            unsigned h0, l0, h1, l1;
            split2(xa[i].x, xa[i].y, h0, l0);
            split2(xa[i].z, xa[i].w, h1, l1);
            *(uint2*)&Ah[r][2 * ac] = make_uint2(h0, h1);
            *(uint2*)&Al[r][2 * ac] = make_uint2(l0, l1);
        }
        {
            const float* w0 = (const float*)&wb0;
            const float* w1 = (const float*)&wb1;
            #pragma unroll
            for (int j = 0; j < 4; j++) {
                unsigned h, l;
                split2(w0[j], w1[j], h, l);
                Bh[4 * bc + j][bsw] = h;
                Bl[4 * bc + j][bsw] = l;
            }
        }
        __syncthreads();

        if (k0 + 32 < DM) {
            #pragma unroll
            for (int i = 0; i < 4; i++)
                xa[i] = *(const float4*)(X + (size_t)(row0 + ar + 32 * i) * DM + k0 + 32 + 4 * ac);
            wb0 = *(const float4*)(W + (size_t)(k0 + 32 + 2 * bk2) * DM + col0 + 4 * bc);
            wb1 = *(const float4*)(W + (size_t)(k0 + 32 + 2 * bk2 + 1) * DM + col0 + 4 * bc);
        }

        #pragma unroll
        for (int ks = 0; ks < 2; ks++) {
            unsigned ah[2][4], al[2][4];
            #pragma unroll
            for (int mi = 0; mi < 2; mi++) {
                int rb = wm * 32 + mi * 16;
                ah[mi][0] = Ah[rb + qr    ][ks * 8 + qc];
                ah[mi][1] = Ah[rb + qr + 8][ks * 8 + qc];
                ah[mi][2] = Ah[rb + qr    ][ks * 8 + qc + 4];
                ah[mi][3] = Ah[rb + qr + 8][ks * 8 + qc + 4];
                al[mi][0] = Al[rb + qr    ][ks * 8 + qc];
                al[mi][1] = Al[rb + qr + 8][ks * 8 + qc];
                al[mi][2] = Al[rb + qr    ][ks * 8 + qc + 4];
                al[mi][3] = Al[rb + qr + 8][ks * 8 + qc + 4];
            }
            #pragma unroll
            for (int j = 0; j < 4; j++) {
                const int nb = wn * 32 + j * 8;
                const int sw = 2 * (((nb >> 2) + (qr >> 2)) & 7);
                unsigned bh[2], bl[2];
                bh[0] = Bh[nb + qr][(ks * 8 + qc    ) ^ sw];
                bh[1] = Bh[nb + qr][(ks * 8 + qc + 4) ^ sw];
                bl[0] = Bl[nb + qr][(ks * 8 + qc    ) ^ sw];
                bl[1] = Bl[nb + qr][(ks * 8 + qc + 4) ^ sw];
                mma_bf16(acc[0][j], ah[0], bh);
                mma_bf16(acc[0][j], ah[0], bl);
                mma_bf16(acc[0][j], al[0], bh);
                mma_bf16(acc[1][j], ah[1], bh);
                mma_bf16(acc[1][j], ah[1], bl);
                mma_bf16(acc[1][j], al[1], bh);
            }
        }
        __syncthreads();
    }

    // Epilogue: RoPE -> split -> bf16 plane scatter.
    const int h = blockIdx.x;
    #pragma unroll
    for (int mi = 0; mi < 2; mi++) {
        #pragma unroll
        for (int half = 0; half < 2; half++) {
            int rg = row0 + wm * 32 + mi * 16 + qr + half * 8;
            int s  = rg & (SEQ - 1);
            int b  = rg >> 11;
            const size_t hb = (size_t)(b * NH + h) * SEQ * HD;
            #pragma unroll
            for (int j = 0; j < 4; j++) {
                float x1 = acc[mi][j][half * 2 + 0];
                float x2 = acc[mi][j][half * 2 + 1];
                int hd = wn * 32 + j * 8 + 2 * qc;
                int pi = hd >> 1;
                float sn = sinT[s * (HD / 2) + pi];
                float cs = cosT[s * (HD / 2) + pi];
                float o1 = x1 * cs - x2 * sn;
                float o2 = x2 * cs + x1 * sn;
                if (mat == 0) { o1 *= 0.125f; o2 *= 0.125f; }   // pre-scale Q
                unsigned hh, ll;
                split2(o1, o2, hh, ll);
                if (mat == 2) {
                    __nv_bfloat162 hv = *reinterpret_cast<__nv_bfloat162*>(&hh);
                    __nv_bfloat162 lv = *reinterpret_cast<__nv_bfloat162*>(&ll);
                    g_vh[hb + (size_t)hd * SEQ + s]       = __low2bfloat16(hv);
                    g_vh[hb + (size_t)(hd + 1) * SEQ + s] = __high2bfloat16(hv);
                    g_vl[hb + (size_t)hd * SEQ + s]       = __low2bfloat16(lv);
                    g_vl[hb + (size_t)(hd + 1) * SEQ + s] = __high2bfloat16(lv);
                } else {
                    __nv_bfloat16* ph = (mat == 0) ? g_qh : g_kh;
                    __nv_bfloat16* pl = (mat == 0) ? g_ql : g_kl;
                    *(unsigned*)&ph[hb + (size_t)s * HD + hd] = hh;
                    *(unsigned*)&pl[hb + (size_t)s * HD + hd] = ll;
                }
            }
        }
    }
}

// ---------------------------------------------------------------------------
// Kernel B: flash attention, 256 thr (8 warps), q-tile 128, kv-tile 64,
// 2-stage cp.async pipeline, LDSM fragment feed. Grid (SEQ/128, B*NH).
// ---------------------------------------------------------------------------
#define PBYTES 8192           // one 64x64 bf16 plane
#define STBYTES (4 * PBYTES)  // 4 planes per stage

extern __shared__ char dynsm[];

__global__ __launch_bounds__(256, 2) void attn_kernel(float* __restrict__ out)
{
    const int tid  = threadIdx.x;
    const int wid  = tid >> 5;
    const int lane = tid & 31;
    const int qr   = lane >> 2;
    const int qc   = lane & 3;
    const int bh   = blockIdx.y;
    const int q0   = blockIdx.x * 128;
    const int wr   = wid * 16;
    const int lrow = tid >> 3;          // loader row (+32*i)
    const int lch  = tid & 7;           // 16B chunk within 128B row

    const size_t hb = (size_t)bh * SEQ * HD;
    const __nv_bfloat16* Kh = g_kh + hb;
    const __nv_bfloat16* Kl = g_kl + hb;
    const __nv_bfloat16* Vh = g_vh + hb;
    const __nv_bfloat16* Vl = g_vl + hb;

    const unsigned sBase = (unsigned)__cvta_generic_to_shared(dynsm);

    // Per-lane LDSM geometry: matrix m = lane/8; row-in-16 = (m&1)*8 + lane%8,
    // chunk parity = m>>1. Covers two n-tiles (rows p*16..p*16+15) per x4.
    const int r0l = ((lane >> 4) & 1) * 8 + (lane & 7);
    const int par = (lane >> 3) & 1;
    unsigned swz[4];
    #pragma unroll
    for (int kk = 0; kk < 4; kk++)
        swz[kk] = (unsigned)((((2 * kk) | par) ^ (r0l & 7)) << 4) + r0l * 128;

    // Q fragments straight from global (hi/lo planes, 32-bit words).
    unsigned fqh[4][4], fql[4][4];
    {
        const unsigned* qwh = (const unsigned*)(g_qh + hb);
        const unsigned* qwl = (const unsigned*)(g_ql + hb);
        const int r0 = (q0 + wr + qr) * (HD / 2);
        const int r1 = r0 + 8 * (HD / 2);
        #pragma unroll
        for (int kk = 0; kk < 4; kk++) {
            fqh[kk][0] = qwh[r0 + kk * 8 + qc];
            fqh[kk][1] = qwh[r1 + kk * 8 + qc];
            fqh[kk][2] = qwh[r0 + kk * 8 + qc + 4];
            fqh[kk][3] = qwh[r1 + kk * 8 + qc + 4];
            fql[kk][0] = qwl[r0 + kk * 8 + qc];
            fql[kk][1] = qwl[r1 + kk * 8 + qc];
            fql[kk][2] = qwl[r0 + kk * 8 + qc + 4];
            fql[kk][3] = qwl[r1 + kk * 8 + qc + 4];
        }
    }

    float m0 = -1e30f, m1 = -1e30f, l0s = 0.f, l1s = 0.f;
    float O[8][4];
    #pragma unroll
    for (int j = 0; j < 8; j++)
        #pragma unroll
        for (int c = 0; c < 4; c++) O[j][c] = 0.f;

    // Tile loader: stage st <- kv tile at kv0. XOR swizzle chunk^(row&7).
    auto issue_tile = [&](int st, int kv0) {
        const unsigned base = sBase + st * STBYTES;
        #pragma unroll
        for (int i = 0; i < 2; i++) {
            const int r = lrow + 32 * i;
            const unsigned so = r * 128 + ((lch ^ (r & 7)) * 16);
            cpa16(base + 0 * PBYTES + so, Kh + (size_t)(kv0 + r) * HD + lch * 8);
            cpa16(base + 1 * PBYTES + so, Kl + (size_t)(kv0 + r) * HD + lch * 8);
            cpa16(base + 2 * PBYTES + so, Vh + (size_t)r * SEQ + kv0 + lch * 8);
            cpa16(base + 3 * PBYTES + so, Vl + (size_t)r * SEQ + kv0 + lch * 8);
        }
        asm volatile("cp.async.commit_group;\n" ::: "memory");
    };

    const int T = SEQ / 64;
    issue_tile(0, 0);
    issue_tile(1, 64);

    for (int t = 0; t < T; t++) {
        if (t + 1 < T) asm volatile("cp.async.wait_group 1;\n" ::: "memory");
        else           asm volatile("cp.async.wait_group 0;\n" ::: "memory");
        __syncthreads();

        const unsigned stb = sBase + (t & 1) * STBYTES;

        // S = Q K^T  (LDSM.x4 feeds 2 n-tiles per instruction)
        float S[8][4];
        #pragma unroll
        for (int j = 0; j < 8; j++)
            #pragma unroll
            for (int c = 0; c < 4; c++) S[j][c] = 0.f;

        #pragma unroll
        for (int kk = 0; kk < 4; kk++) {
            #pragma unroll
            for (int p = 0; p < 4; p++) {
                const unsigned a = stb + p * 2048 + swz[kk];
                unsigned bh[4], bl[4];
                ldsm4(bh[0], bh[1], bh[2], bh[3], a);
                ldsm4(bl[0], bl[1], bl[2], bl[3], a + PBYTES);
                mma_bf16(S[2 * p    ], fqh[kk], bh);
                mma_bf16(S[2 * p    ], fqh[kk], bl);
                mma_bf16(S[2 * p    ], fql[kk], bh);
                mma_bf16(S[2 * p + 1], fqh[kk], bh + 2);
                mma_bf16(S[2 * p + 1], fqh[kk], bl + 2);
                mma_bf16(S[2 * p + 1], fql[kk], bh + 2);
            }
        }

        // Online softmax (rows qr, qr+8)
        float mx0 = -1e30f, mx1 = -1e30f;
        #pragma unroll
        for (int j = 0; j < 8; j++) {
            mx0 = fmaxf(mx0, fmaxf(S[j][0], S[j][1]));
            mx1 = fmaxf(mx1, fmaxf(S[j][2], S[j][3]));
        }
        #pragma unroll
        for (int k = 1; k <= 2; k <<= 1) {
            mx0 = fmaxf(mx0, __shfl_xor_sync(0xffffffffu, mx0, k));
            mx1 = fmaxf(mx1, __shfl_xor_sync(0xffffffffu, mx1, k));
        }
        float nm0 = fmaxf(m0, mx0), nm1 = fmaxf(m1, mx1);
        float sc0 = __expf(m0 - nm0), sc1 = __expf(m1 - nm1);
        m0 = nm0; m1 = nm1;
        float s0 = 0.f, s1 = 0.f;
        #pragma unroll
        for (int j = 0; j < 8; j++) {
            S[j][0] = __expf(S[j][0] - nm0);
            S[j][1] = __expf(S[j][1] - nm0);
            S[j][2] = __expf(S[j][2] - nm1);
            S[j][3] = __expf(S[j][3] - nm1);
            s0 += S[j][0] + S[j][1];
            s1 += S[j][2] + S[j][3];
            O[j][0] *= sc0; O[j][1] *= sc0; O[j][2] *= sc1; O[j][3] *= sc1;
        }
        #pragma unroll
        for (int k = 1; k <= 2; k <<= 1) {
            s0 += __shfl_xor_sync(0xffffffffu, s0, k);
            s1 += __shfl_xor_sync(0xffffffffu, s1, k);
        }
        l0s = l0s * sc0 + s0;
        l1s = l1s * sc1 + s1;

        // O += P V  (P from S registers; C-frag == A-frag layout)
        #pragma unroll
        for (int kk = 0; kk < 4; kk++) {
            unsigned ph[4], pl[4];
            split2(S[2 * kk    ][0], S[2 * kk    ][1], ph[0], pl[0]);
            split2(S[2 * kk    ][2], S[2 * kk    ][3], ph[1], pl[1]);
            split2(S[2 * kk + 1][0], S[2 * kk + 1][1], ph[2], pl[2]);
            split2(S[2 * kk + 1][2], S[2 * kk + 1][3], ph[3], pl[3]);
            #pragma unroll
            for (int p = 0; p < 4; p++) {
                const unsigned a = stb + 2 * PBYTES + p * 2048 + swz[kk];
                unsigned vh[4], vl[4];
                ldsm4(vh[0], vh[1], vh[2], vh[3], a);
                ldsm4(vl[0], vl[1], vl[2], vl[3], a + PBYTES);
                mma_bf16(O[2 * p    ], ph, vh);
                mma_bf16(O[2 * p    ], ph, vl);
                mma_bf16(O[2 * p    ], pl, vh);
                mma_bf16(O[2 * p + 1], ph, vh + 2);
                mma_bf16(O[2 * p + 1], ph, vl + 2);
                mma_bf16(O[2 * p + 1], pl, vh + 2);
            }
        }

        __syncthreads();                 // all reads of buffer (t&1) done
        if (t + 2 < T) issue_tile(t & 1, (t + 2) * 64);
    }

    // Epilogue
    const int b = bh >> 4, h = bh & 15;
    const float inv0 = 1.f / l0s, inv1 = 1.f / l1s;
    const int rg0 = q0 + wr + qr;
    #pragma unroll
    for (int j = 0; j < 8; j++) {
        int col = h * HD + j * 8 + 2 * qc;
        *(float2*)(out + (size_t)(b * SEQ + rg0    ) * DM + col) =
            make_float2(O[j][0] * inv0, O[j][1] * inv0);
        *(float2*)(out + (size_t)(b * SEQ + rg0 + 8) * DM + col) =
            make_float2(O[j][2] * inv1, O[j][3] * inv1);
    }
}

extern "C" void kernel_launch(void* const* d_in, const int* in_sizes, int n_in,
                              void* d_out, int out_size)
{
    const float* X    = (const float*)d_in[0];
    const float* Wq   = (const float*)d_in[1];
    const float* Wk   = (const float*)d_in[2];
    const float* Wv   = (const float*)d_in[3];
    const float* sinT = (const float*)d_in[4];
    const float* cosT = (const float*)d_in[5];
    float* out = (float*)d_out;

    cudaFuncSetAttribute(attn_kernel,
                         cudaFuncAttributeMaxDynamicSharedMemorySize,
                         2 * STBYTES);

    dim3 g1(DM / 64, (BATCH * SEQ) / 128, 3);
    qkv_gemm_rope<<<g1, 256>>>(X, Wq, Wk, Wv, sinT, cosT);

    dim3 g2(SEQ / 128, BATCH * NH);
    attn_kernel<<<g2, 256, 2 * STBYTES>>>(out);
}